// round 13
// baseline (speedup 1.0000x reference)
#include <cuda_runtime.h>
#include <cuda_bf16.h>
#include <mma.h>
#include <math.h>
#include <stdint.h>
using namespace nvcuda;

#define NN 20000
#define EE 320000
#define FIN 128
#define FH 256
#define RR 4
#define NH 4
#define G3 (3*FH)

#define OFF_AGG   ((size_t)0)
#define OFF_H1    (OFF_AGG + (size_t)NN*RR*FH)
#define OFF_H2    (OFF_H1  + (size_t)NN*FH)
#define OFF_Q     (OFF_H2  + (size_t)NN*FH)
#define OFF_K     (OFF_Q   + (size_t)NN*FH)
#define OFF_V     (OFF_K   + (size_t)NN*FH)
#define OFF_ATTN  (OFF_V   + (size_t)NN*FH)
#define OFF_SCORE (OFF_ATTN+ (size_t)NN*FH)
#define OFF_GHX   (OFF_SCORE+(size_t)EE*NH)
#define POOL_SZ   (OFF_GHX + (size_t)NN*G3)
#define OFF_GI    OFF_AGG

__device__ float g_pool[POOL_SZ];
__device__ float g_cnt[NN*RR];
__device__ int   g_smax[NN*NH];
__device__ float g_denom[NN*NH];
__device__ int   g_ticks[4];

// bf16 hi/lo weights, row-major [K][N]
#define WTOT 1146880
__device__ __align__(16) __nv_bfloat16 g_wh[WTOT];
__device__ __align__(16) __nv_bfloat16 g_wl[WTOT];
#define WO_W1 0
#define WO_W2 131072
#define WO_R1 393216
#define WO_R2 425984
#define WO_Q  491520
#define WO_KW 557056
#define WO_VW 622592
#define WO_SK 688128
#define WO_IH 753664
#define WO_HH 950272

__device__ __forceinline__ int f2oi(float f){ int i=__float_as_int(f); return i>=0?i:i^0x7fffffff; }
__device__ __forceinline__ float oi2f(int i){ return __int_as_float(i>=0?i:i^0x7fffffff); }
__device__ __forceinline__ float sigm(float x){ return 1.f/(1.f+expf(-x)); }
__device__ __forceinline__ float4 f4relu(float4 v){ return make_float4(fmaxf(v.x,0.f),fmaxf(v.y,0.f),fmaxf(v.z,0.f),fmaxf(v.w,0.f)); }
__device__ __forceinline__ float4 f4s(float4 v,float s){ return make_float4(v.x*s,v.y*s,v.z*s,v.w*s); }
__device__ __forceinline__ void red4(float* p, float4 v){
    asm volatile("red.global.add.v4.f32 [%0], {%1,%2,%3,%4};"
                 :: "l"(p), "f"(v.x), "f"(v.y), "f"(v.z), "f"(v.w) : "memory");
}

__global__ void k_zero_f4(float4* p, size_t n4){
    for(size_t i=(size_t)blockIdx.x*blockDim.x+threadIdx.x;i<n4;i+=(size_t)gridDim.x*blockDim.x)
        p[i]=make_float4(0.f,0.f,0.f,0.f);
}
__global__ void k_tick0(){ if(threadIdx.x<4) g_ticks[threadIdx.x]=0; }
__global__ void k_init_attn(int* smax, float* denom, int n){
    int v=f2oi(-3.402823466e38f);
    for(int i=blockIdx.x*blockDim.x+threadIdx.x;i<n;i+=gridDim.x*blockDim.x){ smax[i]=v; denom[i]=0.f; }
}
__global__ void k_count(const int* __restrict__ dst, const int* __restrict__ et, float* cnt, int E){
    for(int e=blockIdx.x*blockDim.x+threadIdx.x;e<E;e+=gridDim.x*blockDim.x) atomicAdd(&cnt[dst[e]*RR+et[e]],1.f);
}
__global__ void k_scatter(const float* __restrict__ x, const int* __restrict__ src, const int* __restrict__ dst,
                          const int* __restrict__ et, float* __restrict__ agg, int E, int F, int relu){
    int g=blockIdx.x*blockDim.x+threadIdx.x, w=g>>5, l=g&31, nw=(gridDim.x*blockDim.x)>>5, F4=F>>2;
    for(int e=w;e<E;e+=nw){
        int s=src[e], d=dst[e], r=et[e];
        const float4* xs=(const float4*)(x+(size_t)s*F);
        float* ag=agg+((size_t)d*RR+r)*F;
        for(int i=l;i<F4;i+=32){
            float4 v=xs[i]; if(relu) v=f4relu(v);
            red4(ag+4*i, v);
        }
    }
}
__global__ void k_score(const float* __restrict__ q, const float* __restrict__ kk, const int* __restrict__ src,
                        const int* __restrict__ dst, float* __restrict__ score, int* __restrict__ smax, int E){
    int g=blockIdx.x*blockDim.x+threadIdx.x, w=g>>5, l=g&31, nw=(gridDim.x*blockDim.x)>>5;
    for(int e=w;e<E;e+=nw){
        int s=src[e], d=dst[e];
        const float4* qd=(const float4*)(q+(size_t)d*FH);
        const float4* ks=(const float4*)(kk+(size_t)s*FH);
        float4 a0=qd[l],b0=ks[l],a1=qd[l+32],b1=ks[l+32];
        float p0=a0.x*b0.x+a0.y*b0.y+a0.z*b0.z+a0.w*b0.w;
        float p1=a1.x*b1.x+a1.y*b1.y+a1.z*b1.z+a1.w*b1.w;
        #pragma unroll
        for(int o=8;o>=1;o>>=1){ p0+=__shfl_xor_sync(~0u,p0,o); p1+=__shfl_xor_sync(~0u,p1,o); }
        if((l&15)==0){
            int h=l>>4; float s0=p0*0.125f,s1=p1*0.125f;
            score[(size_t)e*NH+h]=s0; score[(size_t)e*NH+h+2]=s1;
            atomicMax(&smax[d*NH+h],f2oi(s0)); atomicMax(&smax[d*NH+h+2],f2oi(s1));
        }
    }
}
__global__ void k_expsum(float* __restrict__ score, const int* __restrict__ dst, const int* __restrict__ smax,
                         float* __restrict__ denom, int E){
    int tot=E*NH;
    for(int i=blockIdx.x*blockDim.x+threadIdx.x;i<tot;i+=gridDim.x*blockDim.x){
        int e=i>>2,h=i&3,d=dst[e];
        float ex=expf(score[i]-oi2f(smax[d*NH+h]));
        score[i]=ex; atomicAdd(&denom[d*NH+h],ex);
    }
}
__global__ void k_attn(const float* __restrict__ score, const float* __restrict__ denom, const float* __restrict__ v,
                       const int* __restrict__ src, const int* __restrict__ dst, float* __restrict__ out, int E){
    int g=blockIdx.x*blockDim.x+threadIdx.x, w=g>>5, l=g&31, nw=(gridDim.x*blockDim.x)>>5;
    for(int e=w;e<E;e+=nw){
        int s=src[e], d=dst[e], h0=l>>4;
        float a0=score[(size_t)e*NH+h0]/fmaxf(denom[d*NH+h0],1e-16f);
        float a1=score[(size_t)e*NH+h0+2]/fmaxf(denom[d*NH+h0+2],1e-16f);
        const float4* vs=(const float4*)(v+(size_t)s*FH);
        float* od=out+(size_t)d*FH;
        red4(od+4*l,      f4s(vs[l],a0));
        red4(od+4*(l+32), f4s(vs[l+32],a1));
    }
}
__global__ void k_gru(const float* __restrict__ gi, const float* __restrict__ gh, const float* __restrict__ hp, float* __restrict__ out){
    size_t tot=(size_t)NN*FH;
    for(size_t i=(size_t)blockIdx.x*blockDim.x+threadIdx.x;i<tot;i+=(size_t)gridDim.x*blockDim.x){
        size_t n=i/FH; int j=(int)(i%FH);
        const float* a=gi+n*G3; const float* b=gh+n*G3;
        float r=sigm(a[j]+b[j]), z=sigm(a[FH+j]+b[FH+j]);
        float nw=tanhf(a[2*FH+j]+r*b[2*FH+j]);
        out[i]=(1.f-z)*nw+z*hp[i];
    }
}

// fp32 weights -> bf16 hi/lo row-major [K][N]; trans: input is [N][K]
struct WEnt{ const float* W; __nv_bfloat16* dh; __nv_bfloat16* dl; int K,N,trans; };
struct WTab{ int tot; WEnt e[10]; int off[11]; };
__global__ void k_wconv(WTab t){
    int stride=gridDim.x*blockDim.x;
    for(int i=blockIdx.x*blockDim.x+threadIdx.x;i<t.tot;i+=stride){
        int g=0; while(i>=t.off[g+1]) g++;
        WEnt E=t.e[g]; int li=i-t.off[g];
        float w;
        if(!E.trans) w = E.W[li];
        else { int k=li/E.N, n=li-k*E.N; w = E.W[(size_t)n*E.K+k]; }
        __nv_bfloat16 hi=__float2bfloat16_rn(w);
        E.dh[li]=hi;
        E.dl[li]=__float2bfloat16_rn(w-__bfloat162float(hi));
    }
}

// ---------- persistent batched WMMA bf16 GEMM (3-term split, multi-part K) --
// Entry = sum over parts p of A_p[M,Kp] @ B_p  (+bias), accumulated in regs;
// C written once (no atomics). Part modes: 0 plain, 1 relu(A), 2 cnt-scale.
struct Part{ const float* A; const __nv_bfloat16* Bh; const __nv_bfloat16* Bl; int lda,mode,rr,nc; };
struct Entry{
    Part p[5]; int np;
    const float* bias; const float* cnt; float* C;
    int M,N,NC,tiles_n,ntiles;
};
struct Batch{ int ng,total,slot; Entry e[4]; };

#define ALD 24
#define BLD 144
#define A_ELEMS (2*128*ALD)
#define B_ELEMS (2*16*BLD)
#define SMEM_DYN 65536

__global__ __launch_bounds__(256,2) void k_bgemm(Batch bt){
    extern __shared__ char sm[];
    __nv_bfloat16* Ah = (__nv_bfloat16*)sm;
    __nv_bfloat16* Al = Ah + A_ELEMS;
    __nv_bfloat16* Bhs = Al + A_ELEMS;
    __nv_bfloat16* Bls = Bhs + B_ELEMS;
    float* eps = (float*)sm;
    __shared__ int s_t;
    const int tid=threadIdx.x, wid=tid>>5, lid=tid&31;
    const int wr=wid>>1, wc=wid&1;
    const int arow=tid>>1, ak=(tid&1)*8;
    const int brow=tid>>4, bc=(tid&15)*8;

    for(;;){
        if(tid==0) s_t=atomicAdd(&g_ticks[bt.slot],1);
        __syncthreads();
        int t=s_t; if(t>=bt.total) return;
        int g=0,base=0;
        while(t>=base+bt.e[g].ntiles){ base+=bt.e[g].ntiles; g++; }
        const Entry E=bt.e[g];
        int lt=t-base, tm=lt/E.tiles_n, tn=lt-tm*E.tiles_n, m0=tm*128, n0=tn*128;

        wmma::fragment<wmma::accumulator,16,16,16,float> acc[2][4];
        #pragma unroll
        for(int i=0;i<2;i++)
            #pragma unroll
            for(int j=0;j<4;j++) wmma::fill_fragment(acc[i][j],0.f);

        const bool aok=(m0+arow<E.M);
        float4 fa0,fa1; uint4 rbh,rbl;

        // chunk c -> (part pi, k0 within part)
        #define LOADT(c) do{                                                     \
            int cp=(c), pi=0;                                                    \
            while(cp>=E.p[pi].nc){ cp-=E.p[pi].nc; pi++; }                       \
            const Part P=E.p[pi];                                                \
            int k0=cp*16;                                                        \
            if(aok){                                                             \
                const float* ab=P.A+(size_t)(m0+arow)*P.lda+ak+k0;               \
                fa0=*(const float4*)ab; fa1=*(const float4*)(ab+4);              \
                if(P.mode==1){ fa0=f4relu(fa0); fa1=f4relu(fa1); }               \
                else if(P.mode==2){                                              \
                    float asc=1.f/fmaxf(E.cnt[(m0+arow)*RR+P.rr],1.f);           \
                    fa0=f4s(fa0,asc); fa1=f4s(fa1,asc); }                        \
            } else { fa0=make_float4(0,0,0,0); fa1=fa0; }                        \
            const __nv_bfloat16* bh=P.Bh+(size_t)(k0+brow)*E.N+n0+bc;            \
            const __nv_bfloat16* bl=P.Bl+(size_t)(k0+brow)*E.N+n0+bc;            \
            rbh=*(const uint4*)bh; rbl=*(const uint4*)bl;                        \
        }while(0)

        #define STORET(b) do{                                                    \
            __nv_bfloat16* ph=Ah+(b)*128*ALD+arow*ALD+ak;                        \
            __nv_bfloat16* pl=Al+(b)*128*ALD+arow*ALD+ak;                        \
            float fv[8]={fa0.x,fa0.y,fa0.z,fa0.w,fa1.x,fa1.y,fa1.z,fa1.w};       \
            _Pragma("unroll")                                                    \
            for(int u=0;u<8;u++){                                                \
                __nv_bfloat16 h=__float2bfloat16_rn(fv[u]);                      \
                ph[u]=h; pl[u]=__float2bfloat16_rn(fv[u]-__bfloat162float(h));   \
            }                                                                    \
            *(uint4*)(Bhs+(b)*16*BLD+brow*BLD+bc)=rbh;                           \
            *(uint4*)(Bls+(b)*16*BLD+brow*BLD+bc)=rbl;                           \
        }while(0)

        #define COMPUTE(b) do{                                                   \
            const __nv_bfloat16* pa_h=Ah+(b)*128*ALD+(wr*32)*ALD;                \
            const __nv_bfloat16* pa_l=Al+(b)*128*ALD+(wr*32)*ALD;                \
            const __nv_bfloat16* pb_h=Bhs+(b)*16*BLD+wc*64;                      \
            const __nv_bfloat16* pb_l=Bls+(b)*16*BLD+wc*64;                      \
            wmma::fragment<wmma::matrix_a,16,16,16,__nv_bfloat16,wmma::row_major> ah[2],al2[2]; \
            wmma::fragment<wmma::matrix_b,16,16,16,__nv_bfloat16,wmma::row_major> bh[4],bl2[4]; \
            _Pragma("unroll")                                                    \
            for(int i=0;i<2;i++){ wmma::load_matrix_sync(ah[i],pa_h+i*16*ALD,ALD); \
                                  wmma::load_matrix_sync(al2[i],pa_l+i*16*ALD,ALD); } \
            _Pragma("unroll")                                                    \
            for(int j=0;j<4;j++){ wmma::load_matrix_sync(bh[j],pb_h+j*16,BLD);   \
                                  wmma::load_matrix_sync(bl2[j],pb_l+j*16,BLD); } \
            _Pragma("unroll")                                                    \
            for(int i=0;i<2;i++)                                                 \
                _Pragma("unroll")                                                \
                for(int j=0;j<4;j++){                                            \
                    wmma::mma_sync(acc[i][j],ah[i],bh[j],acc[i][j]);             \
                    wmma::mma_sync(acc[i][j],al2[i],bh[j],acc[i][j]);            \
                    wmma::mma_sync(acc[i][j],ah[i],bl2[j],acc[i][j]);            \
                }                                                                \
        }while(0)

        LOADT(0); STORET(0);
        __syncthreads();
        int buf=0;
        for(int c=1;c<E.NC;c++){
            LOADT(c);
            COMPUTE(buf);
            STORET(buf^1);
            __syncthreads();
            buf^=1;
        }
        COMPUTE(buf);
        __syncthreads();
        #undef LOADT
        #undef STORET
        #undef COMPUTE

        // epilogue: per-warp 32x64 region via smem, single write + bias
        float* ep = eps + wid*2048;
        #pragma unroll
        for(int i=0;i<2;i++)
            #pragma unroll
            for(int j=0;j<4;j++)
                wmma::store_matrix_sync(ep + i*16*64 + j*16, acc[i][j], 64, wmma::mem_row_major);
        __syncwarp();
        int c0 = n0 + wc*64 + lid*2;
        float b0v=E.bias[c0], b1v=E.bias[c0+1];
        for(int r2=0;r2<32;r2++){
            int row = m0 + wr*32 + r2;
            if(row >= E.M) break;
            float* crow = E.C + (size_t)row*E.N + c0;
            crow[0]=ep[r2*64+lid*2]+b0v;
            crow[1]=ep[r2*64+lid*2+1]+b1v;
        }
        __syncthreads();
    }
}

static Part mkp(const float* A,int lda,int mode,int rr,const __nv_bfloat16* bh,const __nv_bfloat16* bl,int K){
    Part p; p.A=A; p.lda=lda; p.mode=mode; p.rr=rr; p.Bh=bh; p.Bl=bl; p.nc=K/16; return p;
}
static void fin(Entry& e,const float* bias,const float* cnt,float* C,int M,int N){
    e.bias=bias; e.cnt=cnt; e.C=C; e.M=M; e.N=N;
    e.NC=0; for(int i=0;i<e.np;i++) e.NC+=e.p[i].nc;
    e.tiles_n=N/128; e.ntiles=((M+127)/128)*e.tiles_n;
}

extern "C" void kernel_launch(void* const* d_in, const int* in_sizes, int n_in, void* d_out, int out_size){
    const float* x=(const float*)d_in[0];
    const int* eidx=(const int*)d_in[1];
    const int* src=eidx; const int* dst=eidx+EE;
    const int* et=(const int*)d_in[2];
    const float* hprev=(const float*)d_in[3];
    const float* W1=(const float*)d_in[4];   const float* root1=(const float*)d_in[5];  const float* b1=(const float*)d_in[6];
    const float* W2=(const float*)d_in[7];   const float* root2=(const float*)d_in[8];  const float* b2=(const float*)d_in[9];
    const float* Wq=(const float*)d_in[10];  const float* bq=(const float*)d_in[11];
    const float* Wk=(const float*)d_in[12];  const float* bk=(const float*)d_in[13];
    const float* Wv=(const float*)d_in[14];  const float* bv=(const float*)d_in[15];
    const float* Wskip=(const float*)d_in[16]; const float* bskip=(const float*)d_in[17];
    const float* W_ih=(const float*)d_in[18]; const float* b_ih=(const float*)d_in[19];
    const float* W_hh=(const float*)d_in[20]; const float* b_hh=(const float*)d_in[21];
    float* out=(float*)d_out;

    static float* pool=nullptr; static float* cnt; static int* smax; static float* denom;
    static __nv_bfloat16 *wh,*wl;
    if(!pool){
        void* p;
        cudaGetSymbolAddress(&p,g_pool); pool=(float*)p;
        cudaGetSymbolAddress(&p,g_cnt); cnt=(float*)p;
        cudaGetSymbolAddress(&p,g_smax); smax=(int*)p;
        cudaGetSymbolAddress(&p,g_denom); denom=(float*)p;
        cudaGetSymbolAddress(&p,g_wh); wh=(__nv_bfloat16*)p;
        cudaGetSymbolAddress(&p,g_wl); wl=(__nv_bfloat16*)p;
        cudaFuncSetAttribute(k_bgemm, cudaFuncAttributeMaxDynamicSharedMemorySize, SMEM_DYN);
    }
    float* agg=pool+OFF_AGG; float* h1=pool+OFF_H1; float* h2=pool+OFF_H2;
    float* q=pool+OFF_Q; float* k=pool+OFF_K; float* v=pool+OFF_V;
    float* attn=pool+OFF_ATTN; float* score=pool+OFF_SCORE;
    float* gh=pool+OFF_GHX; float* gi=pool+OFF_GI;

    const int T=256, GB=304;
    int eW=(EE*32+T-1)/T;

    k_tick0<<<1,32>>>();
    { // weight conversion
        WTab wt; int idx=0; int sz[10];
        auto add=[&](const float* W,int K,int N,int tr,int off){ wt.e[idx]=WEnt{W,wh+off,wl+off,K,N,tr}; sz[idx]=N*K; idx++; };
        add(W1,512,256,0,WO_W1);
        add(W2,1024,256,0,WO_W2);
        add(root1,128,256,0,WO_R1);
        add(root2,256,256,0,WO_R2);
        add(Wq,256,256,0,WO_Q); add(Wk,256,256,0,WO_KW); add(Wv,256,256,0,WO_VW); add(Wskip,256,256,0,WO_SK);
        add(W_ih,256,768,1,WO_IH); add(W_hh,256,768,1,WO_HH);
        wt.off[0]=0; for(int i=0;i<10;i++) wt.off[i+1]=wt.off[i]+sz[i];
        wt.tot=wt.off[10];
        k_wconv<<<2048,T>>>(wt);
    }
    k_zero_f4<<<(NN*RR/4+T-1)/T,T>>>((float4*)cnt,(size_t)NN*RR/4);
    k_count<<<(EE+T-1)/T,T>>>(dst,et,cnt,EE);

    k_zero_f4<<<2048,T>>>((float4*)agg,(size_t)NN*RR*FIN/4);
    k_scatter<<<eW,T>>>(x,src,dst,et,agg,EE,FIN,0);
    { // batch 1: fused RGCN1 (root + 4 relations -> one reg-accum entry) + gh
        Batch bt; bt.slot=0; bt.ng=2;
        Entry& e0=bt.e[0]; e0.np=5;
        e0.p[0]=mkp(x,FIN,0,0, wh+WO_R1,wl+WO_R1, FIN);
        for(int r=0;r<RR;r++)
            e0.p[1+r]=mkp(agg+r*FIN,RR*FIN,2,r, wh+WO_W1+r*FIN*FH,wl+WO_W1+r*FIN*FH, FIN);
        fin(e0,b1,cnt,h1,NN,FH);
        Entry& e1=bt.e[1]; e1.np=1;
        e1.p[0]=mkp(hprev,FH,0,0, wh+WO_HH,wl+WO_HH, FH);
        fin(e1,b_hh,cnt,gh,NN,G3);
        bt.total=e0.ntiles+e1.ntiles;
        k_bgemm<<<GB,T,SMEM_DYN>>>(bt);
    }
    k_zero_f4<<<4096,T>>>((float4*)agg,(size_t)NN*RR*FH/4);
    k_scatter<<<eW,T>>>(h1,src,dst,et,agg,EE,FH,1);
    { // batch 2: fused RGCN2
        Batch bt; bt.slot=1; bt.ng=1;
        Entry& e0=bt.e[0]; e0.np=5;
        e0.p[0]=mkp(h1,FH,1,0, wh+WO_R2,wl+WO_R2, FH);
        for(int r=0;r<RR;r++)
            e0.p[1+r]=mkp(agg+r*FH,RR*FH,2,r, wh+WO_W2+r*FH*FH,wl+WO_W2+r*FH*FH, FH);
        fin(e0,b2,cnt,h2,NN,FH);
        bt.total=e0.ntiles;
        k_bgemm<<<GB,T,SMEM_DYN>>>(bt);
    }
    { // batch 3: q/k/v/skip
        Batch bt; bt.slot=2; bt.ng=4;
        const __nv_bfloat16* WH[4]={wh+WO_Q,wh+WO_KW,wh+WO_VW,wh+WO_SK};
        const __nv_bfloat16* WL[4]={wl+WO_Q,wl+WO_KW,wl+WO_VW,wl+WO_SK};
        const float* BS[4]={bq,bk,bv,bskip};
        float* CC[4]={q,k,v,attn};
        bt.total=0;
        for(int i=0;i<4;i++){
            Entry& e=bt.e[i]; e.np=1;
            e.p[0]=mkp(h2,FH,1,0, WH[i],WL[i], FH);
            fin(e,BS[i],cnt,CC[i],NN,FH);
            bt.total+=e.ntiles;
        }
        k_bgemm<<<GB,T,SMEM_DYN>>>(bt);
    }
    k_init_attn<<<(NN*NH+T-1)/T,T>>>(smax,denom,NN*NH);
    k_score<<<eW,T>>>(q,k,src,dst,score,smax,EE);
    k_expsum<<<(EE*NH+T-1)/T,T>>>(score,dst,smax,denom,EE);
    k_attn<<<eW,T>>>(score,denom,v,src,dst,attn,EE);
    { // batch 4: gi
        Batch bt; bt.slot=3; bt.ng=1;
        Entry& e0=bt.e[0]; e0.np=1;
        e0.p[0]=mkp(attn,FH,0,0, wh+WO_IH,wl+WO_IH, FH);
        fin(e0,b_ih,cnt,gi,NN,G3);
        bt.total=e0.ntiles;
        k_bgemm<<<GB,T,SMEM_DYN>>>(bt);
    }
    k_gru<<<((size_t)NN*FH+T-1)/T,T>>>(gi,gh,hprev,out);
}

// round 14
// speedup vs baseline: 1.5345x; 1.5345x over previous
#include <cuda_runtime.h>
#include <cuda_bf16.h>
#include <mma.h>
#include <math.h>
#include <stdint.h>
using namespace nvcuda;

#define NN 20000
#define EE 320000
#define FIN 128
#define FH 256
#define RR 4
#define NH 4
#define G3 (3*FH)

#define OFF_AGG   ((size_t)0)
#define OFF_H1    (OFF_AGG + (size_t)NN*RR*FH)
#define OFF_H2    (OFF_H1  + (size_t)NN*FH)
#define OFF_Q     (OFF_H2  + (size_t)NN*FH)
#define OFF_K     (OFF_Q   + (size_t)NN*FH)
#define OFF_V     (OFF_K   + (size_t)NN*FH)
#define OFF_ATTN  (OFF_V   + (size_t)NN*FH)
#define OFF_SCORE (OFF_ATTN+ (size_t)NN*FH)
#define OFF_GHX   (OFF_SCORE+(size_t)EE*NH)
#define POOL_SZ   (OFF_GHX + (size_t)NN*G3)
#define OFF_GI    OFF_AGG

__device__ float g_pool[POOL_SZ];
__device__ float g_cnt[NN*RR];
__device__ int   g_smax[NN*NH];
__device__ float g_denom[NN*NH];
__device__ int   g_ticks[4];

// bf16 hi/lo weights, row-major [K][N]
#define WTOT 1146880
__device__ __align__(16) __nv_bfloat16 g_wh[WTOT];
__device__ __align__(16) __nv_bfloat16 g_wl[WTOT];
#define WO_W1 0
#define WO_W2 131072
#define WO_R1 393216
#define WO_R2 425984
#define WO_Q  491520
#define WO_KW 557056
#define WO_VW 622592
#define WO_SK 688128
#define WO_IH 753664
#define WO_HH 950272

__device__ __forceinline__ int f2oi(float f){ int i=__float_as_int(f); return i>=0?i:i^0x7fffffff; }
__device__ __forceinline__ float oi2f(int i){ return __int_as_float(i>=0?i:i^0x7fffffff); }
__device__ __forceinline__ float sigm(float x){ return 1.f/(1.f+expf(-x)); }
__device__ __forceinline__ float4 f4relu(float4 v){ return make_float4(fmaxf(v.x,0.f),fmaxf(v.y,0.f),fmaxf(v.z,0.f),fmaxf(v.w,0.f)); }
__device__ __forceinline__ float4 f4s(float4 v,float s){ return make_float4(v.x*s,v.y*s,v.z*s,v.w*s); }
__device__ __forceinline__ void red4(float* p, float4 v){
    asm volatile("red.global.add.v4.f32 [%0], {%1,%2,%3,%4};"
                 :: "l"(p), "f"(v.x), "f"(v.y), "f"(v.z), "f"(v.w) : "memory");
}

__global__ void k_zero_f4(float4* p, size_t n4){
    for(size_t i=(size_t)blockIdx.x*blockDim.x+threadIdx.x;i<n4;i+=(size_t)gridDim.x*blockDim.x)
        p[i]=make_float4(0.f,0.f,0.f,0.f);
}
__global__ void k_tick0(){ if(threadIdx.x<4) g_ticks[threadIdx.x]=0; }
__global__ void k_init_attn(int* smax, float* denom, int n){
    int v=f2oi(-3.402823466e38f);
    for(int i=blockIdx.x*blockDim.x+threadIdx.x;i<n;i+=gridDim.x*blockDim.x){ smax[i]=v; denom[i]=0.f; }
}
__global__ void k_count(const int* __restrict__ dst, const int* __restrict__ et, float* cnt, int E){
    for(int e=blockIdx.x*blockDim.x+threadIdx.x;e<E;e+=gridDim.x*blockDim.x) atomicAdd(&cnt[dst[e]*RR+et[e]],1.f);
}
__global__ void k_scatter(const float* __restrict__ x, const int* __restrict__ src, const int* __restrict__ dst,
                          const int* __restrict__ et, float* __restrict__ agg, int E, int F, int relu){
    int g=blockIdx.x*blockDim.x+threadIdx.x, w=g>>5, l=g&31, nw=(gridDim.x*blockDim.x)>>5, F4=F>>2;
    for(int e=w;e<E;e+=nw){
        int s=src[e], d=dst[e], r=et[e];
        const float4* xs=(const float4*)(x+(size_t)s*F);
        float* ag=agg+((size_t)d*RR+r)*F;
        for(int i=l;i<F4;i+=32){
            float4 v=xs[i]; if(relu) v=f4relu(v);
            red4(ag+4*i, v);
        }
    }
}
__global__ void k_score(const float* __restrict__ q, const float* __restrict__ kk, const int* __restrict__ src,
                        const int* __restrict__ dst, float* __restrict__ score, int* __restrict__ smax, int E){
    int g=blockIdx.x*blockDim.x+threadIdx.x, w=g>>5, l=g&31, nw=(gridDim.x*blockDim.x)>>5;
    for(int e=w;e<E;e+=nw){
        int s=src[e], d=dst[e];
        const float4* qd=(const float4*)(q+(size_t)d*FH);
        const float4* ks=(const float4*)(kk+(size_t)s*FH);
        float4 a0=qd[l],b0=ks[l],a1=qd[l+32],b1=ks[l+32];
        float p0=a0.x*b0.x+a0.y*b0.y+a0.z*b0.z+a0.w*b0.w;
        float p1=a1.x*b1.x+a1.y*b1.y+a1.z*b1.z+a1.w*b1.w;
        #pragma unroll
        for(int o=8;o>=1;o>>=1){ p0+=__shfl_xor_sync(~0u,p0,o); p1+=__shfl_xor_sync(~0u,p1,o); }
        if((l&15)==0){
            int h=l>>4; float s0=p0*0.125f,s1=p1*0.125f;
            score[(size_t)e*NH+h]=s0; score[(size_t)e*NH+h+2]=s1;
            atomicMax(&smax[d*NH+h],f2oi(s0)); atomicMax(&smax[d*NH+h+2],f2oi(s1));
        }
    }
}
__global__ void k_expsum(float* __restrict__ score, const int* __restrict__ dst, const int* __restrict__ smax,
                         float* __restrict__ denom, int E){
    int tot=E*NH;
    for(int i=blockIdx.x*blockDim.x+threadIdx.x;i<tot;i+=gridDim.x*blockDim.x){
        int e=i>>2,h=i&3,d=dst[e];
        float ex=expf(score[i]-oi2f(smax[d*NH+h]));
        score[i]=ex; atomicAdd(&denom[d*NH+h],ex);
    }
}
__global__ void k_attn(const float* __restrict__ score, const float* __restrict__ denom, const float* __restrict__ v,
                       const int* __restrict__ src, const int* __restrict__ dst, float* __restrict__ out, int E){
    int g=blockIdx.x*blockDim.x+threadIdx.x, w=g>>5, l=g&31, nw=(gridDim.x*blockDim.x)>>5;
    for(int e=w;e<E;e+=nw){
        int s=src[e], d=dst[e], h0=l>>4;
        float a0=score[(size_t)e*NH+h0]/fmaxf(denom[d*NH+h0],1e-16f);
        float a1=score[(size_t)e*NH+h0+2]/fmaxf(denom[d*NH+h0+2],1e-16f);
        const float4* vs=(const float4*)(v+(size_t)s*FH);
        float* od=out+(size_t)d*FH;
        red4(od+4*l,      f4s(vs[l],a0));
        red4(od+4*(l+32), f4s(vs[l+32],a1));
    }
}
__global__ void k_gru(const float* __restrict__ gi, const float* __restrict__ gh, const float* __restrict__ hp, float* __restrict__ out){
    size_t tot=(size_t)NN*FH;
    for(size_t i=(size_t)blockIdx.x*blockDim.x+threadIdx.x;i<tot;i+=(size_t)gridDim.x*blockDim.x){
        size_t n=i/FH; int j=(int)(i%FH);
        const float* a=gi+n*G3; const float* b=gh+n*G3;
        float r=sigm(a[j]+b[j]), z=sigm(a[FH+j]+b[FH+j]);
        float nw=tanhf(a[2*FH+j]+r*b[2*FH+j]);
        out[i]=(1.f-z)*nw+z*hp[i];
    }
}

// fp32 weights -> bf16 hi/lo row-major [K][N]; trans: input is [N][K]
struct WEnt{ const float* W; __nv_bfloat16* dh; __nv_bfloat16* dl; int K,N,trans; };
struct WTab{ int tot; WEnt e[10]; int off[11]; };
__global__ void k_wconv(WTab t){
    int stride=gridDim.x*blockDim.x;
    for(int i=blockIdx.x*blockDim.x+threadIdx.x;i<t.tot;i+=stride){
        int g=0; while(i>=t.off[g+1]) g++;
        WEnt E=t.e[g]; int li=i-t.off[g];
        float w;
        if(!E.trans) w = E.W[li];
        else { int k=li/E.N, n=li-k*E.N; w = E.W[(size_t)n*E.K+k]; }
        __nv_bfloat16 hi=__float2bfloat16_rn(w);
        E.dh[li]=hi;
        E.dl[li]=__float2bfloat16_rn(w-__bfloat162float(hi));
    }
}

// ---------- persistent batched WMMA bf16 GEMM (3-term split, multi-part K) --
// Entry = sum over parts p of A_p[M,Kp] @ B_p  (+bias), accumulated in regs;
// C written once (no atomics). Part state loaded once per part transition.
struct Part{ const float* A; const __nv_bfloat16* Bh; const __nv_bfloat16* Bl; int lda,mode,rr,nc; };
struct Entry{
    Part p[5]; int np;
    const float* bias; const float* cnt; float* C;
    int M,N,NC,tiles_n,ntiles;
};
struct Batch{ int ng,total,slot; Entry e[4]; };

#define ALD 24
#define BLD 144
#define A_ELEMS (2*128*ALD)
#define B_ELEMS (2*16*BLD)
#define SMEM_DYN 65536

__global__ __launch_bounds__(256,2) void k_bgemm(Batch bt){
    extern __shared__ char sm[];
    __nv_bfloat16* Ah = (__nv_bfloat16*)sm;
    __nv_bfloat16* Al = Ah + A_ELEMS;
    __nv_bfloat16* Bhs = Al + A_ELEMS;
    __nv_bfloat16* Bls = Bhs + B_ELEMS;
    float* eps = (float*)sm;
    __shared__ int s_t;
    const int tid=threadIdx.x, wid=tid>>5, lid=tid&31;
    const int wr=wid>>1, wc=wid&1;
    const int arow=tid>>1, ak=(tid&1)*8;
    const int brow=tid>>4, bc=(tid&15)*8;

    for(;;){
        if(tid==0) s_t=atomicAdd(&g_ticks[bt.slot],1);
        __syncthreads();
        int t=s_t; if(t>=bt.total) return;
        int g=0,base=0;
        while(t>=base+bt.e[g].ntiles){ base+=bt.e[g].ntiles; g++; }
        // scalars read once (param/const space), no struct copy
        const int EM=bt.e[g].M, EN=bt.e[g].N, ENC=bt.e[g].NC, Etn=bt.e[g].tiles_n;
        const float* Ebias=bt.e[g].bias;
        const float* Ecnt =bt.e[g].cnt;
        float* EC=bt.e[g].C;
        int lt=t-base, tm=lt/Etn, tn=lt-tm*Etn, m0=tm*128, n0=tn*128;

        wmma::fragment<wmma::accumulator,16,16,16,float> acc[2][4];
        #pragma unroll
        for(int i=0;i<2;i++)
            #pragma unroll
            for(int j=0;j<4;j++) wmma::fill_fragment(acc[i][j],0.f);

        const bool aok=(m0+arow<EM);
        float4 fa0,fa1; uint4 rbh,rbl;

        // part cursor: P loaded once per part (dynamic index, but infrequent)
        int pi=0, cp=0;
        Part P = bt.e[g].p[0];
        float asc = 1.f;
        if(P.mode==2) asc = aok ? 1.f/fmaxf(Ecnt[(m0+arow)*RR+P.rr],1.f) : 0.f;

        #define PART_NEXT() do{                                                  \
            cp++;                                                                \
            if(cp==P.nc){                                                        \
                pi++; cp=0; P=bt.e[g].p[pi];                                     \
                if(P.mode==2) asc = aok ? 1.f/fmaxf(Ecnt[(m0+arow)*RR+P.rr],1.f) : 0.f; \
            }                                                                    \
        }while(0)

        #define LOADT() do{                                                      \
            int k0=cp*16;                                                        \
            if(aok){                                                             \
                const float* ab=P.A+(size_t)(m0+arow)*P.lda+ak+k0;               \
                fa0=*(const float4*)ab; fa1=*(const float4*)(ab+4);              \
                if(P.mode==1){ fa0=f4relu(fa0); fa1=f4relu(fa1); }               \
                else if(P.mode==2){ fa0=f4s(fa0,asc); fa1=f4s(fa1,asc); }        \
            } else { fa0=make_float4(0,0,0,0); fa1=fa0; }                        \
            rbh=*(const uint4*)(P.Bh+(size_t)(k0+brow)*EN+n0+bc);                \
            rbl=*(const uint4*)(P.Bl+(size_t)(k0+brow)*EN+n0+bc);                \
        }while(0)

        #define STORET(b) do{                                                    \
            __nv_bfloat16* ph=Ah+(b)*128*ALD+arow*ALD+ak;                        \
            __nv_bfloat16* pl=Al+(b)*128*ALD+arow*ALD+ak;                        \
            float fv[8]={fa0.x,fa0.y,fa0.z,fa0.w,fa1.x,fa1.y,fa1.z,fa1.w};       \
            _Pragma("unroll")                                                    \
            for(int u=0;u<8;u++){                                                \
                __nv_bfloat16 h=__float2bfloat16_rn(fv[u]);                      \
                ph[u]=h; pl[u]=__float2bfloat16_rn(fv[u]-__bfloat162float(h));   \
            }                                                                    \
            *(uint4*)(Bhs+(b)*16*BLD+brow*BLD+bc)=rbh;                           \
            *(uint4*)(Bls+(b)*16*BLD+brow*BLD+bc)=rbl;                           \
        }while(0)

        #define COMPUTE(b) do{                                                   \
            const __nv_bfloat16* pa_h=Ah+(b)*128*ALD+(wr*32)*ALD;                \
            const __nv_bfloat16* pa_l=Al+(b)*128*ALD+(wr*32)*ALD;                \
            const __nv_bfloat16* pb_h=Bhs+(b)*16*BLD+wc*64;                      \
            const __nv_bfloat16* pb_l=Bls+(b)*16*BLD+wc*64;                      \
            wmma::fragment<wmma::matrix_a,16,16,16,__nv_bfloat16,wmma::row_major> ah[2],al2[2]; \
            wmma::fragment<wmma::matrix_b,16,16,16,__nv_bfloat16,wmma::row_major> bh[4],bl2[4]; \
            _Pragma("unroll")                                                    \
            for(int i=0;i<2;i++){ wmma::load_matrix_sync(ah[i],pa_h+i*16*ALD,ALD); \
                                  wmma::load_matrix_sync(al2[i],pa_l+i*16*ALD,ALD); } \
            _Pragma("unroll")                                                    \
            for(int j=0;j<4;j++){ wmma::load_matrix_sync(bh[j],pb_h+j*16,BLD);   \
                                  wmma::load_matrix_sync(bl2[j],pb_l+j*16,BLD); } \
            _Pragma("unroll")                                                    \
            for(int i=0;i<2;i++)                                                 \
                _Pragma("unroll")                                                \
                for(int j=0;j<4;j++){                                            \
                    wmma::mma_sync(acc[i][j],ah[i],bh[j],acc[i][j]);             \
                    wmma::mma_sync(acc[i][j],al2[i],bh[j],acc[i][j]);            \
                    wmma::mma_sync(acc[i][j],ah[i],bl2[j],acc[i][j]);            \
                }                                                                \
        }while(0)

        LOADT(); STORET(0);
        __syncthreads();
        int buf=0;
        for(int c=1;c<ENC;c++){
            PART_NEXT();
            LOADT();
            COMPUTE(buf);
            STORET(buf^1);
            __syncthreads();
            buf^=1;
        }
        COMPUTE(buf);
        __syncthreads();
        #undef PART_NEXT
        #undef LOADT
        #undef STORET
        #undef COMPUTE

        // epilogue: per-warp 32x64 region via smem, single write + bias
        float* ep = eps + wid*2048;
        #pragma unroll
        for(int i=0;i<2;i++)
            #pragma unroll
            for(int j=0;j<4;j++)
                wmma::store_matrix_sync(ep + i*16*64 + j*16, acc[i][j], 64, wmma::mem_row_major);
        __syncwarp();
        int c0 = n0 + wc*64 + lid*2;
        float b0v=Ebias[c0], b1v=Ebias[c0+1];
        for(int r2=0;r2<32;r2++){
            int row = m0 + wr*32 + r2;
            if(row >= EM) break;
            float* crow = EC + (size_t)row*EN + c0;
            crow[0]=ep[r2*64+lid*2]+b0v;
            crow[1]=ep[r2*64+lid*2+1]+b1v;
        }
        __syncthreads();
    }
}

static Part mkp(const float* A,int lda,int mode,int rr,const __nv_bfloat16* bh,const __nv_bfloat16* bl,int K){
    Part p; p.A=A; p.lda=lda; p.mode=mode; p.rr=rr; p.Bh=bh; p.Bl=bl; p.nc=K/16; return p;
}
static void fin(Entry& e,const float* bias,const float* cnt,float* C,int M,int N){
    e.bias=bias; e.cnt=cnt; e.C=C; e.M=M; e.N=N;
    e.NC=0; for(int i=0;i<e.np;i++) e.NC+=e.p[i].nc;
    e.tiles_n=N/128; e.ntiles=((M+127)/128)*e.tiles_n;
}

extern "C" void kernel_launch(void* const* d_in, const int* in_sizes, int n_in, void* d_out, int out_size){
    const float* x=(const float*)d_in[0];
    const int* eidx=(const int*)d_in[1];
    const int* src=eidx; const int* dst=eidx+EE;
    const int* et=(const int*)d_in[2];
    const float* hprev=(const float*)d_in[3];
    const float* W1=(const float*)d_in[4];   const float* root1=(const float*)d_in[5];  const float* b1=(const float*)d_in[6];
    const float* W2=(const float*)d_in[7];   const float* root2=(const float*)d_in[8];  const float* b2=(const float*)d_in[9];
    const float* Wq=(const float*)d_in[10];  const float* bq=(const float*)d_in[11];
    const float* Wk=(const float*)d_in[12];  const float* bk=(const float*)d_in[13];
    const float* Wv=(const float*)d_in[14];  const float* bv=(const float*)d_in[15];
    const float* Wskip=(const float*)d_in[16]; const float* bskip=(const float*)d_in[17];
    const float* W_ih=(const float*)d_in[18]; const float* b_ih=(const float*)d_in[19];
    const float* W_hh=(const float*)d_in[20]; const float* b_hh=(const float*)d_in[21];
    float* out=(float*)d_out;

    static float* pool=nullptr; static float* cnt; static int* smax; static float* denom;
    static __nv_bfloat16 *wh,*wl;
    if(!pool){
        void* p;
        cudaGetSymbolAddress(&p,g_pool); pool=(float*)p;
        cudaGetSymbolAddress(&p,g_cnt); cnt=(float*)p;
        cudaGetSymbolAddress(&p,g_smax); smax=(int*)p;
        cudaGetSymbolAddress(&p,g_denom); denom=(float*)p;
        cudaGetSymbolAddress(&p,g_wh); wh=(__nv_bfloat16*)p;
        cudaGetSymbolAddress(&p,g_wl); wl=(__nv_bfloat16*)p;
        cudaFuncSetAttribute(k_bgemm, cudaFuncAttributeMaxDynamicSharedMemorySize, SMEM_DYN);
    }
    float* agg=pool+OFF_AGG; float* h1=pool+OFF_H1; float* h2=pool+OFF_H2;
    float* q=pool+OFF_Q; float* k=pool+OFF_K; float* v=pool+OFF_V;
    float* attn=pool+OFF_ATTN; float* score=pool+OFF_SCORE;
    float* gh=pool+OFF_GHX; float* gi=pool+OFF_GI;

    const int T=256, GB=304;
    int eW=(EE*32+T-1)/T;

    k_tick0<<<1,32>>>();
    { // weight conversion
        WTab wt; int idx=0; int sz[10];
        auto add=[&](const float* W,int K,int N,int tr,int off){ wt.e[idx]=WEnt{W,wh+off,wl+off,K,N,tr}; sz[idx]=N*K; idx++; };
        add(W1,512,256,0,WO_W1);
        add(W2,1024,256,0,WO_W2);
        add(root1,128,256,0,WO_R1);
        add(root2,256,256,0,WO_R2);
        add(Wq,256,256,0,WO_Q); add(Wk,256,256,0,WO_KW); add(Wv,256,256,0,WO_VW); add(Wskip,256,256,0,WO_SK);
        add(W_ih,256,768,1,WO_IH); add(W_hh,256,768,1,WO_HH);
        wt.off[0]=0; for(int i=0;i<10;i++) wt.off[i+1]=wt.off[i]+sz[i];
        wt.tot=wt.off[10];
        k_wconv<<<2048,T>>>(wt);
    }
    k_zero_f4<<<(NN*RR/4+T-1)/T,T>>>((float4*)cnt,(size_t)NN*RR/4);
    k_count<<<(EE+T-1)/T,T>>>(dst,et,cnt,EE);

    k_zero_f4<<<2048,T>>>((float4*)agg,(size_t)NN*RR*FIN/4);
    k_scatter<<<eW,T>>>(x,src,dst,et,agg,EE,FIN,0);
    { // batch 1: fused RGCN1 (root + 4 relations, reg-accum) + gh
        Batch bt; bt.slot=0; bt.ng=2;
        Entry& e0=bt.e[0]; e0.np=5;
        e0.p[0]=mkp(x,FIN,0,0, wh+WO_R1,wl+WO_R1, FIN);
        for(int r=0;r<RR;r++)
            e0.p[1+r]=mkp(agg+r*FIN,RR*FIN,2,r, wh+WO_W1+r*FIN*FH,wl+WO_W1+r*FIN*FH, FIN);
        fin(e0,b1,cnt,h1,NN,FH);
        Entry& e1=bt.e[1]; e1.np=1;
        e1.p[0]=mkp(hprev,FH,0,0, wh+WO_HH,wl+WO_HH, FH);
        fin(e1,b_hh,cnt,gh,NN,G3);
        bt.total=e0.ntiles+e1.ntiles;
        k_bgemm<<<GB,T,SMEM_DYN>>>(bt);
    }
    k_zero_f4<<<4096,T>>>((float4*)agg,(size_t)NN*RR*FH/4);
    k_scatter<<<eW,T>>>(h1,src,dst,et,agg,EE,FH,1);
    { // batch 2: fused RGCN2
        Batch bt; bt.slot=1; bt.ng=1;
        Entry& e0=bt.e[0]; e0.np=5;
        e0.p[0]=mkp(h1,FH,1,0, wh+WO_R2,wl+WO_R2, FH);
        for(int r=0;r<RR;r++)
            e0.p[1+r]=mkp(agg+r*FH,RR*FH,2,r, wh+WO_W2+r*FH*FH,wl+WO_W2+r*FH*FH, FH);
        fin(e0,b2,cnt,h2,NN,FH);
        bt.total=e0.ntiles;
        k_bgemm<<<GB,T,SMEM_DYN>>>(bt);
    }
    { // batch 3: q/k/v/skip
        Batch bt; bt.slot=2; bt.ng=4;
        const __nv_bfloat16* WH[4]={wh+WO_Q,wh+WO_KW,wh+WO_VW,wh+WO_SK};
        const __nv_bfloat16* WL[4]={wl+WO_Q,wl+WO_KW,wl+WO_VW,wl+WO_SK};
        const float* BS[4]={bq,bk,bv,bskip};
        float* CC[4]={q,k,v,attn};
        bt.total=0;
        for(int i=0;i<4;i++){
            Entry& e=bt.e[i]; e.np=1;
            e.p[0]=mkp(h2,FH,1,0, WH[i],WL[i], FH);
            fin(e,BS[i],cnt,CC[i],NN,FH);
            bt.total+=e.ntiles;
        }
        k_bgemm<<<GB,T,SMEM_DYN>>>(bt);
    }
    k_init_attn<<<(NN*NH+T-1)/T,T>>>(smax,denom,NN*NH);
    k_score<<<eW,T>>>(q,k,src,dst,score,smax,EE);
    k_expsum<<<(EE*NH+T-1)/T,T>>>(score,dst,smax,denom,EE);
    k_attn<<<eW,T>>>(score,denom,v,src,dst,attn,EE);
    { // batch 4: gi
        Batch bt; bt.slot=3; bt.ng=1;
        Entry& e0=bt.e[0]; e0.np=1;
        e0.p[0]=mkp(attn,FH,0,0, wh+WO_IH,wl+WO_IH, FH);
        fin(e0,b_ih,cnt,gi,NN,G3);
        bt.total=e0.ntiles;
        k_bgemm<<<GB,T,SMEM_DYN>>>(bt);
    }
    k_gru<<<((size_t)NN*FH+T-1)/T,T>>>(gi,gh,hprev,out);
}

// round 16
// speedup vs baseline: 1.6002x; 1.0428x over previous
#include <cuda_runtime.h>
#include <cuda_bf16.h>
#include <mma.h>
#include <math.h>
#include <stdint.h>
using namespace nvcuda;

#define NN 20000
#define EE 320000
#define FIN 128
#define FH 256
#define RR 4
#define NH 4
#define G3 (3*FH)

#define OFF_AGG   ((size_t)0)
#define OFF_H1    (OFF_AGG + (size_t)NN*RR*FH)
#define OFF_H2    (OFF_H1  + (size_t)NN*FH)
#define OFF_Q     (OFF_H2  + (size_t)NN*FH)
#define OFF_K     (OFF_Q   + (size_t)NN*FH)
#define OFF_V     (OFF_K   + (size_t)NN*FH)
#define OFF_ATTN  (OFF_V   + (size_t)NN*FH)
#define OFF_SCORE (OFF_ATTN+ (size_t)NN*FH)
#define OFF_GHX   (OFF_SCORE+(size_t)EE*NH)
#define POOL_SZ   (OFF_GHX + (size_t)NN*G3)
#define OFF_GI    OFF_AGG

__device__ float g_pool[POOL_SZ];
__device__ float g_cnt[NN*RR];
__device__ int   g_smax[NN*NH];
__device__ float g_denom[NN*NH];
__device__ int   g_ticks[4];

// bf16 hi/lo weights, row-major [K][N]
#define WTOT 1146880
__device__ __align__(16) __nv_bfloat16 g_wh[WTOT];
__device__ __align__(16) __nv_bfloat16 g_wl[WTOT];
#define WO_W1 0
#define WO_W2 131072
#define WO_R1 393216
#define WO_R2 425984
#define WO_Q  491520
#define WO_KW 557056
#define WO_VW 622592
#define WO_SK 688128
#define WO_IH 753664
#define WO_HH 950272

__device__ __forceinline__ int f2oi(float f){ int i=__float_as_int(f); return i>=0?i:i^0x7fffffff; }
__device__ __forceinline__ float oi2f(int i){ return __int_as_float(i>=0?i:i^0x7fffffff); }
__device__ __forceinline__ float sigm(float x){ return 1.f/(1.f+expf(-x)); }
__device__ __forceinline__ float4 f4relu(float4 v){ return make_float4(fmaxf(v.x,0.f),fmaxf(v.y,0.f),fmaxf(v.z,0.f),fmaxf(v.w,0.f)); }
__device__ __forceinline__ float4 f4s(float4 v,float s){ return make_float4(v.x*s,v.y*s,v.z*s,v.w*s); }
__device__ __forceinline__ void red4(float* p, float4 v){
    asm volatile("red.global.add.v4.f32 [%0], {%1,%2,%3,%4};"
                 :: "l"(p), "f"(v.x), "f"(v.y), "f"(v.z), "f"(v.w) : "memory");
}

__global__ void k_zero_f4(float4* p, size_t n4){
    for(size_t i=(size_t)blockIdx.x*blockDim.x+threadIdx.x;i<n4;i+=(size_t)gridDim.x*blockDim.x)
        p[i]=make_float4(0.f,0.f,0.f,0.f);
}
__global__ void k_tick0(){ if(threadIdx.x<4) g_ticks[threadIdx.x]=0; }
__global__ void k_seed_bias(float* C, const float* bias, int M, int N){
    size_t tot=(size_t)M*N;
    for(size_t i=(size_t)blockIdx.x*blockDim.x+threadIdx.x;i<tot;i+=(size_t)gridDim.x*blockDim.x) C[i]=bias[i%(size_t)N];
}
__global__ void k_init_attn(int* smax, float* denom, int n){
    int v=f2oi(-3.402823466e38f);
    for(int i=blockIdx.x*blockDim.x+threadIdx.x;i<n;i+=gridDim.x*blockDim.x){ smax[i]=v; denom[i]=0.f; }
}
__global__ void k_count(const int* __restrict__ dst, const int* __restrict__ et, float* cnt, int E){
    for(int e=blockIdx.x*blockDim.x+threadIdx.x;e<E;e+=gridDim.x*blockDim.x) atomicAdd(&cnt[dst[e]*RR+et[e]],1.f);
}
__global__ void k_scatter(const float* __restrict__ x, const int* __restrict__ src, const int* __restrict__ dst,
                          const int* __restrict__ et, float* __restrict__ agg, int E, int F, int relu){
    int g=blockIdx.x*blockDim.x+threadIdx.x, w=g>>5, l=g&31, nw=(gridDim.x*blockDim.x)>>5, F4=F>>2;
    for(int e=w;e<E;e+=nw){
        int s=src[e], d=dst[e], r=et[e];
        const float4* xs=(const float4*)(x+(size_t)s*F);
        float* ag=agg+((size_t)d*RR+r)*F;
        for(int i=l;i<F4;i+=32){
            float4 v=xs[i]; if(relu) v=f4relu(v);
            red4(ag+4*i, v);
        }
    }
}
__global__ void k_score(const float* __restrict__ q, const float* __restrict__ kk, const int* __restrict__ src,
                        const int* __restrict__ dst, float* __restrict__ score, int* __restrict__ smax, int E){
    int g=blockIdx.x*blockDim.x+threadIdx.x, w=g>>5, l=g&31, nw=(gridDim.x*blockDim.x)>>5;
    for(int e=w;e<E;e+=nw){
        int s=src[e], d=dst[e];
        const float4* qd=(const float4*)(q+(size_t)d*FH);
        const float4* ks=(const float4*)(kk+(size_t)s*FH);
        float4 a0=qd[l],b0=ks[l],a1=qd[l+32],b1=ks[l+32];
        float p0=a0.x*b0.x+a0.y*b0.y+a0.z*b0.z+a0.w*b0.w;
        float p1=a1.x*b1.x+a1.y*b1.y+a1.z*b1.z+a1.w*b1.w;
        #pragma unroll
        for(int o=8;o>=1;o>>=1){ p0+=__shfl_xor_sync(~0u,p0,o); p1+=__shfl_xor_sync(~0u,p1,o); }
        if((l&15)==0){
            int h=l>>4; float s0=p0*0.125f,s1=p1*0.125f;
            score[(size_t)e*NH+h]=s0; score[(size_t)e*NH+h+2]=s1;
            atomicMax(&smax[d*NH+h],f2oi(s0)); atomicMax(&smax[d*NH+h+2],f2oi(s1));
        }
    }
}
__global__ void k_expsum(float* __restrict__ score, const int* __restrict__ dst, const int* __restrict__ smax,
                         float* __restrict__ denom, int E){
    int tot=E*NH;
    for(int i=blockIdx.x*blockDim.x+threadIdx.x;i<tot;i+=gridDim.x*blockDim.x){
        int e=i>>2,h=i&3,d=dst[e];
        float ex=expf(score[i]-oi2f(smax[d*NH+h]));
        score[i]=ex; atomicAdd(&denom[d*NH+h],ex);
    }
}
__global__ void k_attn(const float* __restrict__ score, const float* __restrict__ denom, const float* __restrict__ v,
                       const int* __restrict__ src, const int* __restrict__ dst, float* __restrict__ out, int E){
    int g=blockIdx.x*blockDim.x+threadIdx.x, w=g>>5, l=g&31, nw=(gridDim.x*blockDim.x)>>5;
    for(int e=w;e<E;e+=nw){
        int s=src[e], d=dst[e], h0=l>>4;
        float a0=score[(size_t)e*NH+h0]/fmaxf(denom[d*NH+h0],1e-16f);
        float a1=score[(size_t)e*NH+h0+2]/fmaxf(denom[d*NH+h0+2],1e-16f);
        const float4* vs=(const float4*)(v+(size_t)s*FH);
        float* od=out+(size_t)d*FH;
        red4(od+4*l,      f4s(vs[l],a0));
        red4(od+4*(l+32), f4s(vs[l+32],a1));
    }
}
__global__ void k_gru(const float* __restrict__ gi, const float* __restrict__ gh, const float* __restrict__ hp, float* __restrict__ out){
    size_t tot=(size_t)NN*FH;
    for(size_t i=(size_t)blockIdx.x*blockDim.x+threadIdx.x;i<tot;i+=(size_t)gridDim.x*blockDim.x){
        size_t n=i/FH; int j=(int)(i%FH);
        const float* a=gi+n*G3; const float* b=gh+n*G3;
        float r=sigm(a[j]+b[j]), z=sigm(a[FH+j]+b[FH+j]);
        float nw=tanhf(a[2*FH+j]+r*b[2*FH+j]);
        out[i]=(1.f-z)*nw+z*hp[i];
    }
}

// fp32 weights -> bf16 hi/lo row-major [K][N]; trans: input is [N][K]
struct WEnt{ const float* W; __nv_bfloat16* dh; __nv_bfloat16* dl; int K,N,trans; };
struct WTab{ int tot; WEnt e[10]; int off[11]; };
__global__ void k_wconv(WTab t){
    int stride=gridDim.x*blockDim.x;
    for(int i=blockIdx.x*blockDim.x+threadIdx.x;i<t.tot;i+=stride){
        int g=0; while(i>=t.off[g+1]) g++;
        WEnt E=t.e[g]; int li=i-t.off[g];
        float w;
        if(!E.trans) w = E.W[li];
        else { int k=li/E.N, n=li-k*E.N; w = E.W[(size_t)n*E.K+k]; }
        __nv_bfloat16 hi=__float2bfloat16_rn(w);
        E.dh[li]=hi;
        E.dl[li]=__float2bfloat16_rn(w-__bfloat162float(hi));
    }
}

// ---------- persistent batched WMMA bf16 GEMM (3-term split, BK=32) ---------
// R12 structure (split entries, atomic epilogues). Pipeline per chunk:
// LOADT -> STORET(other buf) -> COMPUTE(cur) -> sync  (staged regs released early)
struct Entry{
    const float* A; const __nv_bfloat16* Bh; const __nv_bfloat16* Bl;
    const float* bias; const float* cnt; float* C;
    int M,N,K,lda,ldb, atomic_ep, mode, rr, tiles_n, ntiles;
};
struct Batch{ int ng,total,slot; Entry e[6]; };

#define BK 32
#define ALD 40
#define BLD 144
#define A_ELEMS (2*128*ALD)
#define B_ELEMS (2*BK*BLD)
#define SMEM_DYN 77824

__global__ __launch_bounds__(256,2) void k_bgemm(Batch bt){
    extern __shared__ char sm[];
    __nv_bfloat16* Ah = (__nv_bfloat16*)sm;
    __nv_bfloat16* Al = Ah + A_ELEMS;
    __nv_bfloat16* Bhs = Al + A_ELEMS;
    __nv_bfloat16* Bls = Bhs + B_ELEMS;
    float* eps = (float*)sm;
    __shared__ int s_t;
    const int tid=threadIdx.x, wid=tid>>5, lid=tid&31;
    const int wr=wid>>1, wc=wid&1;
    const int arow=tid>>1, ak=(tid&1)*16;     // 2 thr/row, 16 fp32 each
    const int brow=tid>>4, bc=(tid&15)*8;     // rows brow & brow+16

    for(;;){
        if(tid==0) s_t=atomicAdd(&g_ticks[bt.slot],1);
        __syncthreads();
        int t=s_t; if(t>=bt.total) return;
        int g=0,base=0;
        while(t>=base+bt.e[g].ntiles){ base+=bt.e[g].ntiles; g++; }
        const Entry E=bt.e[g];
        int lt=t-base, tm=lt/E.tiles_n, tn=lt-tm*E.tiles_n, m0=tm*128, n0=tn*128;

        wmma::fragment<wmma::accumulator,16,16,16,float> acc[2][4];
        #pragma unroll
        for(int i=0;i<2;i++)
            #pragma unroll
            for(int j=0;j<4;j++) wmma::fill_fragment(acc[i][j],0.f);

        const bool aok=(m0+arow<E.M);
        const float* abase = E.A + (size_t)(m0+arow)*E.lda + ak;
        float asc=1.f;
        if(E.mode==2 && aok) asc = 1.f/fmaxf(E.cnt[(m0+arow)*RR+E.rr],1.f);
        const __nv_bfloat16* bhg = E.Bh + (size_t)brow*E.ldb + n0 + bc;
        const __nv_bfloat16* blg = E.Bl + (size_t)brow*E.ldb + n0 + bc;

        float4 fa[4]; uint4 rbh0,rbh1,rbl0,rbl1;
        #define LOADT(k0) do{                                                   \
            if(aok){                                                            \
                fa[0]=*(const float4*)(abase+(k0));                             \
                fa[1]=*(const float4*)(abase+(k0)+4);                           \
                fa[2]=*(const float4*)(abase+(k0)+8);                           \
                fa[3]=*(const float4*)(abase+(k0)+12);                          \
                if(E.mode==1){ fa[0]=f4relu(fa[0]); fa[1]=f4relu(fa[1]);        \
                               fa[2]=f4relu(fa[2]); fa[3]=f4relu(fa[3]); }      \
                else if(E.mode==2){ fa[0]=f4s(fa[0],asc); fa[1]=f4s(fa[1],asc); \
                                    fa[2]=f4s(fa[2],asc); fa[3]=f4s(fa[3],asc);} \
            } else { fa[0]=make_float4(0,0,0,0); fa[1]=fa[0]; fa[2]=fa[0]; fa[3]=fa[0]; } \
            rbh0=*(const uint4*)(bhg+(size_t)(k0)*E.ldb);                       \
            rbh1=*(const uint4*)(bhg+(size_t)((k0)+16)*E.ldb);                  \
            rbl0=*(const uint4*)(blg+(size_t)(k0)*E.ldb);                       \
            rbl1=*(const uint4*)(blg+(size_t)((k0)+16)*E.ldb);                  \
        }while(0)

        #define STORET(b) do{                                                    \
            __nv_bfloat16* ph=Ah+(b)*128*ALD+arow*ALD+ak;                        \
            __nv_bfloat16* pl=Al+(b)*128*ALD+arow*ALD+ak;                        \
            const float* fv=(const float*)fa;                                    \
            _Pragma("unroll")                                                    \
            for(int u=0;u<16;u++){                                               \
                __nv_bfloat16 h=__float2bfloat16_rn(fv[u]);                      \
                ph[u]=h; pl[u]=__float2bfloat16_rn(fv[u]-__bfloat162float(h));   \
            }                                                                    \
            *(uint4*)(Bhs+(b)*BK*BLD+brow*BLD+bc)=rbh0;                          \
            *(uint4*)(Bhs+(b)*BK*BLD+(brow+16)*BLD+bc)=rbh1;                     \
            *(uint4*)(Bls+(b)*BK*BLD+brow*BLD+bc)=rbl0;                          \
            *(uint4*)(Bls+(b)*BK*BLD+(brow+16)*BLD+bc)=rbl1;                     \
        }while(0)

        #define COMPUTE(b) do{                                                   \
            _Pragma("unroll")                                                    \
            for(int s=0;s<2;s++){                                                \
                const __nv_bfloat16* pa_h=Ah+(b)*128*ALD+(wr*32)*ALD+s*16;       \
                const __nv_bfloat16* pa_l=Al+(b)*128*ALD+(wr*32)*ALD+s*16;       \
                const __nv_bfloat16* pb_h=Bhs+(b)*BK*BLD+s*16*BLD+wc*64;         \
                const __nv_bfloat16* pb_l=Bls+(b)*BK*BLD+s*16*BLD+wc*64;         \
                wmma::fragment<wmma::matrix_a,16,16,16,__nv_bfloat16,wmma::row_major> ah[2],al2[2]; \
                wmma::fragment<wmma::matrix_b,16,16,16,__nv_bfloat16,wmma::row_major> bh[4],bl2[4]; \
                _Pragma("unroll")                                                \
                for(int i=0;i<2;i++){ wmma::load_matrix_sync(ah[i],pa_h+i*16*ALD,ALD); \
                                      wmma::load_matrix_sync(al2[i],pa_l+i*16*ALD,ALD); } \
                _Pragma("unroll")                                                \
                for(int j=0;j<4;j++){ wmma::load_matrix_sync(bh[j],pb_h+j*16,BLD); \
                                      wmma::load_matrix_sync(bl2[j],pb_l+j*16,BLD); } \
                _Pragma("unroll")                                                \
                for(int i=0;i<2;i++)                                             \
                    _Pragma("unroll")                                            \
                    for(int j=0;j<4;j++){                                        \
                        wmma::mma_sync(acc[i][j],ah[i],bh[j],acc[i][j]);         \
                        wmma::mma_sync(acc[i][j],al2[i],bh[j],acc[i][j]);        \
                        wmma::mma_sync(acc[i][j],ah[i],bl2[j],acc[i][j]);        \
                    }                                                            \
            }                                                                    \
        }while(0)

        LOADT(0); STORET(0);
        __syncthreads();
        int buf=0;
        for(int k0=BK;k0<E.K;k0+=BK){
            LOADT(k0);
            STORET(buf^1);      // staged regs released before compute
            COMPUTE(buf);
            __syncthreads();
            buf^=1;
        }
        COMPUTE(buf);
        __syncthreads();
        #undef LOADT
        #undef STORET
        #undef COMPUTE

        // epilogue: per-warp 32x64 region via smem
        float* ep = eps + wid*2048;
        #pragma unroll
        for(int i=0;i<2;i++)
            #pragma unroll
            for(int j=0;j<4;j++)
                wmma::store_matrix_sync(ep + i*16*64 + j*16, acc[i][j], 64, wmma::mem_row_major);
        __syncwarp();
        int c0 = n0 + wc*64 + lid*2;
        for(int r2=0;r2<32;r2++){
            int row = m0 + wr*32 + r2;
            if(row >= E.M) break;
            float v0=ep[r2*64+lid*2], v1=ep[r2*64+lid*2+1];
            float* crow = E.C + (size_t)row*E.N + c0;
            if(E.atomic_ep){ atomicAdd(crow,v0); atomicAdd(crow+1,v1); }
            else { crow[0]=v0+E.bias[c0]; crow[1]=v1+E.bias[c0+1]; }
        }
        __syncthreads();
    }
}

static Entry mkent(const float* A,int lda,const __nv_bfloat16* bh,const __nv_bfloat16* bl,int ldb,
                   float* C,const float* bias,int M,int N,int K,int atomic_ep,int mode,int rr,const float* cnt){
    Entry e; e.A=A; e.Bh=bh; e.Bl=bl; e.bias=bias; e.cnt=cnt; e.C=C;
    e.M=M; e.N=N; e.K=K; e.lda=lda; e.ldb=ldb;
    e.atomic_ep=atomic_ep; e.mode=mode; e.rr=rr;
    e.tiles_n=N/128; e.ntiles=((M+127)/128)*e.tiles_n;
    return e;
}

extern "C" void kernel_launch(void* const* d_in, const int* in_sizes, int n_in, void* d_out, int out_size){
    const float* x=(const float*)d_in[0];
    const int* eidx=(const int*)d_in[1];
    const int* src=eidx; const int* dst=eidx+EE;
    const int* et=(const int*)d_in[2];
    const float* hprev=(const float*)d_in[3];
    const float* W1=(const float*)d_in[4];   const float* root1=(const float*)d_in[5];  const float* b1=(const float*)d_in[6];
    const float* W2=(const float*)d_in[7];   const float* root2=(const float*)d_in[8];  const float* b2=(const float*)d_in[9];
    const float* Wq=(const float*)d_in[10];  const float* bq=(const float*)d_in[11];
    const float* Wk=(const float*)d_in[12];  const float* bk=(const float*)d_in[13];
    const float* Wv=(const float*)d_in[14];  const float* bv=(const float*)d_in[15];
    const float* Wskip=(const float*)d_in[16]; const float* bskip=(const float*)d_in[17];
    const float* W_ih=(const float*)d_in[18]; const float* b_ih=(const float*)d_in[19];
    const float* W_hh=(const float*)d_in[20]; const float* b_hh=(const float*)d_in[21];
    float* out=(float*)d_out;

    static float* pool=nullptr; static float* cnt; static int* smax; static float* denom;
    static __nv_bfloat16 *wh,*wl;
    if(!pool){
        void* p;
        cudaGetSymbolAddress(&p,g_pool); pool=(float*)p;
        cudaGetSymbolAddress(&p,g_cnt); cnt=(float*)p;
        cudaGetSymbolAddress(&p,g_smax); smax=(int*)p;
        cudaGetSymbolAddress(&p,g_denom); denom=(float*)p;
        cudaGetSymbolAddress(&p,g_wh); wh=(__nv_bfloat16*)p;
        cudaGetSymbolAddress(&p,g_wl); wl=(__nv_bfloat16*)p;
        cudaFuncSetAttribute(k_bgemm, cudaFuncAttributeMaxDynamicSharedMemorySize, SMEM_DYN);
    }
    float* agg=pool+OFF_AGG; float* h1=pool+OFF_H1; float* h2=pool+OFF_H2;
    float* q=pool+OFF_Q; float* k=pool+OFF_K; float* v=pool+OFF_V;
    float* attn=pool+OFF_ATTN; float* score=pool+OFF_SCORE;
    float* gh=pool+OFF_GHX; float* gi=pool+OFF_GI;

    const int T=256, GB=304;
    int eW=(EE*32+T-1)/T;

    k_tick0<<<1,32>>>();
    { // weight conversion
        WTab wt; int idx=0; int sz[10];
        auto add=[&](const float* W,int K,int N,int tr,int off){ wt.e[idx]=WEnt{W,wh+off,wl+off,K,N,tr}; sz[idx]=N*K; idx++; };
        add(W1,512,256,0,WO_W1);
        add(W2,1024,256,0,WO_W2);
        add(root1,128,256,0,WO_R1);
        add(root2,256,256,0,WO_R2);
        add(Wq,256,256,0,WO_Q); add(Wk,256,256,0,WO_KW); add(Wv,256,256,0,WO_VW); add(Wskip,256,256,0,WO_SK);
        add(W_ih,256,768,1,WO_IH); add(W_hh,256,768,1,WO_HH);
        wt.off[0]=0; for(int i=0;i<10;i++) wt.off[i+1]=wt.off[i]+sz[i];
        wt.tot=wt.off[10];
        k_wconv<<<2048,T>>>(wt);
    }
    k_zero_f4<<<(NN*RR/4+T-1)/T,T>>>((float4*)cnt,(size_t)NN*RR/4);
    k_count<<<(EE+T-1)/T,T>>>(dst,et,cnt,EE);

    k_zero_f4<<<2048,T>>>((float4*)agg,(size_t)NN*RR*FIN/4);
    k_scatter<<<eW,T>>>(x,src,dst,et,agg,EE,FIN,0);
    k_seed_bias<<<1024,T>>>(h1,b1,NN,FH);
    { // batch 1: RGCN1 (root + 4 relations, atomic) + gh
        Batch bt; bt.slot=0; bt.ng=6;
        bt.e[0]=mkent(x,FIN, wh+WO_R1,wl+WO_R1,FH, h1,nullptr, NN,FH,FIN, 1,0,0,nullptr);
        for(int r=0;r<RR;r++)
            bt.e[1+r]=mkent(agg+r*FIN,RR*FIN, wh+WO_W1+r*FIN*FH,wl+WO_W1+r*FIN*FH,FH,
                            h1,nullptr, NN,FH,FIN, 1,2,r,cnt);
        bt.e[5]=mkent(hprev,FH, wh+WO_HH,wl+WO_HH,G3, gh,b_hh, NN,G3,FH, 0,0,0,nullptr);
        bt.total=0; for(int i=0;i<bt.ng;i++) bt.total+=bt.e[i].ntiles;
        k_bgemm<<<GB,T,SMEM_DYN>>>(bt);
    }
    k_zero_f4<<<4096,T>>>((float4*)agg,(size_t)NN*RR*FH/4);
    k_scatter<<<eW,T>>>(h1,src,dst,et,agg,EE,FH,1);
    k_seed_bias<<<1024,T>>>(h2,b2,NN,FH);
    { // batch 2: RGCN2
        Batch bt; bt.slot=1; bt.ng=5;
        bt.e[0]=mkent(h1,FH, wh+WO_R2,wl+WO_R2,FH, h2,nullptr, NN,FH,FH, 1,1,0,nullptr);
        for(int r=0;r<RR;r++)
            bt.e[1+r]=mkent(agg+r*FH,RR*FH, wh+WO_W2+r*FH*FH,wl+WO_W2+r*FH*FH,FH,
                            h2,nullptr, NN,FH,FH, 1,2,r,cnt);
        bt.total=0; for(int i=0;i<bt.ng;i++) bt.total+=bt.e[i].ntiles;
        k_bgemm<<<GB,T,SMEM_DYN>>>(bt);
    }
    { // batch 3: q/k/v/skip
        Batch bt; bt.slot=2; bt.ng=4;
        bt.e[0]=mkent(h2,FH, wh+WO_Q, wl+WO_Q, FH, q,   bq,   NN,FH,FH, 0,1,0,nullptr);
        bt.e[1]=mkent(h2,FH, wh+WO_KW,wl+WO_KW,FH, k,   bk,   NN,FH,FH, 0,1,0,nullptr);
        bt.e[2]=mkent(h2,FH, wh+WO_VW,wl+WO_VW,FH, v,   bv,   NN,FH,FH, 0,1,0,nullptr);
        bt.e[3]=mkent(h2,FH, wh+WO_SK,wl+WO_SK,FH, attn,bskip,NN,FH,FH, 0,1,0,nullptr);
        bt.total=0; for(int i=0;i<bt.ng;i++) bt.total+=bt.e[i].ntiles;
        k_bgemm<<<GB,T,SMEM_DYN>>>(bt);
    }
    k_init_attn<<<(NN*NH+T-1)/T,T>>>(smax,denom,NN*NH);
    k_score<<<eW,T>>>(q,k,src,dst,score,smax,EE);
    k_expsum<<<(EE*NH+T-1)/T,T>>>(score,dst,smax,denom,EE);
    k_attn<<<eW,T>>>(score,denom,v,src,dst,attn,EE);
    { // batch 4: gi
        Batch bt; bt.slot=3; bt.ng=1;
        bt.e[0]=mkent(attn,FH, wh+WO_IH,wl+WO_IH,G3, gi,b_ih, NN,G3,FH, 0,0,0,nullptr);
        bt.total=bt.e[0].ntiles;
        k_bgemm<<<GB,T,SMEM_DYN>>>(bt);
    }
    k_gru<<<((size_t)NN*FH+T-1)/T,T>>>(gi,gh,hprev,out);
}

// round 17
// speedup vs baseline: 1.6105x; 1.0065x over previous
#include <cuda_runtime.h>
#include <cuda_bf16.h>
#include <mma.h>
#include <math.h>
#include <stdint.h>
using namespace nvcuda;

#define NN 20000
#define EE 320000
#define FIN 128
#define FH 256
#define RR 4
#define NH 4
#define G3 (3*FH)

#define OFF_AGG   ((size_t)0)
#define OFF_H1    (OFF_AGG + (size_t)NN*RR*FH)
#define OFF_H2    (OFF_H1  + (size_t)NN*FH)
#define OFF_Q     (OFF_H2  + (size_t)NN*FH)
#define OFF_K     (OFF_Q   + (size_t)NN*FH)
#define OFF_V     (OFF_K   + (size_t)NN*FH)
#define OFF_ATTN  (OFF_V   + (size_t)NN*FH)
#define OFF_SCORE (OFF_ATTN+ (size_t)NN*FH)
#define OFF_GHX   (OFF_SCORE+(size_t)EE*NH)
#define POOL_SZ   (OFF_GHX + (size_t)NN*G3)
#define OFF_GI    OFF_AGG

__device__ float g_pool[POOL_SZ];
__device__ float g_cnt[NN*RR];
__device__ int   g_smax[NN*NH];
__device__ float g_denom[NN*NH];
__device__ int   g_ticks[4];

// bf16 hi/lo weights, row-major [K][N]
#define WTOT 1146880
__device__ __align__(16) __nv_bfloat16 g_wh[WTOT];
__device__ __align__(16) __nv_bfloat16 g_wl[WTOT];
#define WO_W1 0
#define WO_W2 131072
#define WO_R1 393216
#define WO_R2 425984
#define WO_Q  491520
#define WO_KW 557056
#define WO_VW 622592
#define WO_SK 688128
#define WO_IH 753664
#define WO_HH 950272

__device__ __forceinline__ int f2oi(float f){ int i=__float_as_int(f); return i>=0?i:i^0x7fffffff; }
__device__ __forceinline__ float oi2f(int i){ return __int_as_float(i>=0?i:i^0x7fffffff); }
__device__ __forceinline__ float sigm(float x){ return 1.f/(1.f+expf(-x)); }
__device__ __forceinline__ float4 f4relu(float4 v){ return make_float4(fmaxf(v.x,0.f),fmaxf(v.y,0.f),fmaxf(v.z,0.f),fmaxf(v.w,0.f)); }
__device__ __forceinline__ float4 f4s(float4 v,float s){ return make_float4(v.x*s,v.y*s,v.z*s,v.w*s); }
__device__ __forceinline__ void red4(float* p, float4 v){
    asm volatile("red.global.add.v4.f32 [%0], {%1,%2,%3,%4};"
                 :: "l"(p), "f"(v.x), "f"(v.y), "f"(v.z), "f"(v.w) : "memory");
}

__global__ void k_zero_f4(float4* p, size_t n4){
    for(size_t i=(size_t)blockIdx.x*blockDim.x+threadIdx.x;i<n4;i+=(size_t)gridDim.x*blockDim.x)
        p[i]=make_float4(0.f,0.f,0.f,0.f);
}
__global__ void k_tick0(){ if(threadIdx.x<4) g_ticks[threadIdx.x]=0; }
__global__ void k_seed_bias(float* C, const float* bias, int M, int N){
    size_t tot=(size_t)M*N;
    for(size_t i=(size_t)blockIdx.x*blockDim.x+threadIdx.x;i<tot;i+=(size_t)gridDim.x*blockDim.x) C[i]=bias[i%(size_t)N];
}
__global__ void k_init_attn(int* smax, float* denom, int n){
    int v=f2oi(-3.402823466e38f);
    for(int i=blockIdx.x*blockDim.x+threadIdx.x;i<n;i+=gridDim.x*blockDim.x){ smax[i]=v; denom[i]=0.f; }
}
__global__ void k_count(const int* __restrict__ dst, const int* __restrict__ et, float* cnt, int E){
    for(int e=blockIdx.x*blockDim.x+threadIdx.x;e<E;e+=gridDim.x*blockDim.x) atomicAdd(&cnt[dst[e]*RR+et[e]],1.f);
}
__global__ void k_scatter(const float* __restrict__ x, const int* __restrict__ src, const int* __restrict__ dst,
                          const int* __restrict__ et, float* __restrict__ agg, int E, int F, int relu){
    int g=blockIdx.x*blockDim.x+threadIdx.x, w=g>>5, l=g&31, nw=(gridDim.x*blockDim.x)>>5, F4=F>>2;
    for(int e=w;e<E;e+=nw){
        int s=src[e], d=dst[e], r=et[e];
        const float4* xs=(const float4*)(x+(size_t)s*F);
        float* ag=agg+((size_t)d*RR+r)*F;
        for(int i=l;i<F4;i+=32){
            float4 v=xs[i]; if(relu) v=f4relu(v);
            red4(ag+4*i, v);
        }
    }
}
__global__ void k_score(const float* __restrict__ q, const float* __restrict__ kk, const int* __restrict__ src,
                        const int* __restrict__ dst, float* __restrict__ score, int* __restrict__ smax, int E){
    int g=blockIdx.x*blockDim.x+threadIdx.x, w=g>>5, l=g&31, nw=(gridDim.x*blockDim.x)>>5;
    for(int e=w;e<E;e+=nw){
        int s=src[e], d=dst[e];
        const float4* qd=(const float4*)(q+(size_t)d*FH);
        const float4* ks=(const float4*)(kk+(size_t)s*FH);
        float4 a0=qd[l],b0=ks[l],a1=qd[l+32],b1=ks[l+32];
        float p0=a0.x*b0.x+a0.y*b0.y+a0.z*b0.z+a0.w*b0.w;
        float p1=a1.x*b1.x+a1.y*b1.y+a1.z*b1.z+a1.w*b1.w;
        #pragma unroll
        for(int o=8;o>=1;o>>=1){ p0+=__shfl_xor_sync(~0u,p0,o); p1+=__shfl_xor_sync(~0u,p1,o); }
        if((l&15)==0){
            int h=l>>4; float s0=p0*0.125f,s1=p1*0.125f;
            score[(size_t)e*NH+h]=s0; score[(size_t)e*NH+h+2]=s1;
            atomicMax(&smax[d*NH+h],f2oi(s0)); atomicMax(&smax[d*NH+h+2],f2oi(s1));
        }
    }
}
__global__ void k_expsum(float* __restrict__ score, const int* __restrict__ dst, const int* __restrict__ smax,
                         float* __restrict__ denom, int E){
    int tot=E*NH;
    for(int i=blockIdx.x*blockDim.x+threadIdx.x;i<tot;i+=gridDim.x*blockDim.x){
        int e=i>>2,h=i&3,d=dst[e];
        float ex=expf(score[i]-oi2f(smax[d*NH+h]));
        score[i]=ex; atomicAdd(&denom[d*NH+h],ex);
    }
}
__global__ void k_attn(const float* __restrict__ score, const float* __restrict__ denom, const float* __restrict__ v,
                       const int* __restrict__ src, const int* __restrict__ dst, float* __restrict__ out, int E){
    int g=blockIdx.x*blockDim.x+threadIdx.x, w=g>>5, l=g&31, nw=(gridDim.x*blockDim.x)>>5;
    for(int e=w;e<E;e+=nw){
        int s=src[e], d=dst[e], h0=l>>4;
        float a0=score[(size_t)e*NH+h0]/fmaxf(denom[d*NH+h0],1e-16f);
        float a1=score[(size_t)e*NH+h0+2]/fmaxf(denom[d*NH+h0+2],1e-16f);
        const float4* vs=(const float4*)(v+(size_t)s*FH);
        float* od=out+(size_t)d*FH;
        red4(od+4*l,      f4s(vs[l],a0));
        red4(od+4*(l+32), f4s(vs[l+32],a1));
    }
}
__global__ void k_gru(const float* __restrict__ gi, const float* __restrict__ gh, const float* __restrict__ hp, float* __restrict__ out){
    size_t tot=(size_t)NN*FH;
    for(size_t i=(size_t)blockIdx.x*blockDim.x+threadIdx.x;i<tot;i+=(size_t)gridDim.x*blockDim.x){
        size_t n=i/FH; int j=(int)(i%FH);
        const float* a=gi+n*G3; const float* b=gh+n*G3;
        float r=sigm(a[j]+b[j]), z=sigm(a[FH+j]+b[FH+j]);
        float nw=tanhf(a[2*FH+j]+r*b[2*FH+j]);
        out[i]=(1.f-z)*nw+z*hp[i];
    }
}

// fp32 weights -> bf16 hi/lo row-major [K][N]; trans: input is [N][K]
struct WEnt{ const float* W; __nv_bfloat16* dh; __nv_bfloat16* dl; int K,N,trans; };
struct WTab{ int tot; WEnt e[10]; int off[11]; };
__global__ void k_wconv(WTab t){
    int stride=gridDim.x*blockDim.x;
    for(int i=blockIdx.x*blockDim.x+threadIdx.x;i<t.tot;i+=stride){
        int g=0; while(i>=t.off[g+1]) g++;
        WEnt E=t.e[g]; int li=i-t.off[g];
        float w;
        if(!E.trans) w = E.W[li];
        else { int k=li/E.N, n=li-k*E.N; w = E.W[(size_t)n*E.K+k]; }
        __nv_bfloat16 hi=__float2bfloat16_rn(w);
        E.dh[li]=hi;
        E.dl[li]=__float2bfloat16_rn(w-__bfloat162float(hi));
    }
}

// ---------- persistent batched WMMA bf16 GEMM (3-term split, BK=32) ---------
// Vectorized A staging: packed bf16x2 cvt + uint4 STS (4 vec stores vs 32 scalar)
struct Entry{
    const float* A; const __nv_bfloat16* Bh; const __nv_bfloat16* Bl;
    const float* bias; const float* cnt; float* C;
    int M,N,K,lda,ldb, atomic_ep, mode, rr, tiles_n, ntiles;
};
struct Batch{ int ng,total,slot; Entry e[6]; };

#define BK 32
#define ALD 40
#define BLD 144
#define A_ELEMS (2*128*ALD)
#define B_ELEMS (2*BK*BLD)
#define SMEM_DYN 77824

__global__ __launch_bounds__(256,2) void k_bgemm(Batch bt){
    extern __shared__ char sm[];
    __nv_bfloat16* Ah = (__nv_bfloat16*)sm;
    __nv_bfloat16* Al = Ah + A_ELEMS;
    __nv_bfloat16* Bhs = Al + A_ELEMS;
    __nv_bfloat16* Bls = Bhs + B_ELEMS;
    float* eps = (float*)sm;
    __shared__ int s_t;
    const int tid=threadIdx.x, wid=tid>>5, lid=tid&31;
    const int wr=wid>>1, wc=wid&1;
    const int arow=tid>>1, ak=(tid&1)*16;     // 2 thr/row, 16 fp32 each
    const int brow=tid>>4, bc=(tid&15)*8;     // rows brow & brow+16

    for(;;){
        if(tid==0) s_t=atomicAdd(&g_ticks[bt.slot],1);
        __syncthreads();
        int t=s_t; if(t>=bt.total) return;
        int g=0,base=0;
        while(t>=base+bt.e[g].ntiles){ base+=bt.e[g].ntiles; g++; }
        const Entry E=bt.e[g];
        int lt=t-base, tm=lt/E.tiles_n, tn=lt-tm*E.tiles_n, m0=tm*128, n0=tn*128;

        wmma::fragment<wmma::accumulator,16,16,16,float> acc[2][4];
        #pragma unroll
        for(int i=0;i<2;i++)
            #pragma unroll
            for(int j=0;j<4;j++) wmma::fill_fragment(acc[i][j],0.f);

        const bool aok=(m0+arow<E.M);
        const float* abase = E.A + (size_t)(m0+arow)*E.lda + ak;
        float asc=1.f;
        if(E.mode==2 && aok) asc = 1.f/fmaxf(E.cnt[(m0+arow)*RR+E.rr],1.f);
        const __nv_bfloat16* bhg = E.Bh + (size_t)brow*E.ldb + n0 + bc;
        const __nv_bfloat16* blg = E.Bl + (size_t)brow*E.ldb + n0 + bc;

        float4 fa[4]; uint4 rbh0,rbh1,rbl0,rbl1;
        #define LOADT(k0) do{                                                   \
            if(aok){                                                            \
                fa[0]=*(const float4*)(abase+(k0));                             \
                fa[1]=*(const float4*)(abase+(k0)+4);                           \
                fa[2]=*(const float4*)(abase+(k0)+8);                           \
                fa[3]=*(const float4*)(abase+(k0)+12);                          \
                if(E.mode==1){ fa[0]=f4relu(fa[0]); fa[1]=f4relu(fa[1]);        \
                               fa[2]=f4relu(fa[2]); fa[3]=f4relu(fa[3]); }      \
                else if(E.mode==2){ fa[0]=f4s(fa[0],asc); fa[1]=f4s(fa[1],asc); \
                                    fa[2]=f4s(fa[2],asc); fa[3]=f4s(fa[3],asc);} \
            } else { fa[0]=make_float4(0,0,0,0); fa[1]=fa[0]; fa[2]=fa[0]; fa[3]=fa[0]; } \
            rbh0=*(const uint4*)(bhg+(size_t)(k0)*E.ldb);                       \
            rbh1=*(const uint4*)(bhg+(size_t)((k0)+16)*E.ldb);                  \
            rbl0=*(const uint4*)(blg+(size_t)(k0)*E.ldb);                       \
            rbl1=*(const uint4*)(blg+(size_t)((k0)+16)*E.ldb);                  \
        }while(0)

        // packed hi/lo conversion + vector STS (4x uint4 instead of 32 scalar)
        #define STORET(b) do{                                                    \
            __nv_bfloat16* ph=Ah+(b)*128*ALD+arow*ALD+ak;                        \
            __nv_bfloat16* pl=Al+(b)*128*ALD+arow*ALD+ak;                        \
            const float* fv=(const float*)fa;                                    \
            uint32_t hw[8], lw[8];                                               \
            _Pragma("unroll")                                                    \
            for(int p2=0;p2<8;p2++){                                             \
                float f0=fv[2*p2], f1=fv[2*p2+1];                                \
                __nv_bfloat162 hp2=__floats2bfloat162_rn(f0,f1);                 \
                float2 hf=__bfloat1622float2(hp2);                               \
                __nv_bfloat162 lp2=__floats2bfloat162_rn(f0-hf.x,f1-hf.y);       \
                hw[p2]=*(uint32_t*)&hp2; lw[p2]=*(uint32_t*)&lp2;                \
            }                                                                    \
            *(uint4*)ph     = *(uint4*)&hw[0];                                   \
            *(uint4*)(ph+8) = *(uint4*)&hw[4];                                   \
            *(uint4*)pl     = *(uint4*)&lw[0];                                   \
            *(uint4*)(pl+8) = *(uint4*)&lw[4];                                   \
            *(uint4*)(Bhs+(b)*BK*BLD+brow*BLD+bc)=rbh0;                          \
            *(uint4*)(Bhs+(b)*BK*BLD+(brow+16)*BLD+bc)=rbh1;                     \
            *(uint4*)(Bls+(b)*BK*BLD+brow*BLD+bc)=rbl0;                          \
            *(uint4*)(Bls+(b)*BK*BLD+(brow+16)*BLD+bc)=rbl1;                     \
        }while(0)

        #define COMPUTE(b) do{                                                   \
            _Pragma("unroll")                                                    \
            for(int s=0;s<2;s++){                                                \
                const __nv_bfloat16* pa_h=Ah+(b)*128*ALD+(wr*32)*ALD+s*16;       \
                const __nv_bfloat16* pa_l=Al+(b)*128*ALD+(wr*32)*ALD+s*16;       \
                const __nv_bfloat16* pb_h=Bhs+(b)*BK*BLD+s*16*BLD+wc*64;         \
                const __nv_bfloat16* pb_l=Bls+(b)*BK*BLD+s*16*BLD+wc*64;         \
                wmma::fragment<wmma::matrix_a,16,16,16,__nv_bfloat16,wmma::row_major> ah[2],al2[2]; \
                wmma::fragment<wmma::matrix_b,16,16,16,__nv_bfloat16,wmma::row_major> bh[4],bl2[4]; \
                _Pragma("unroll")                                                \
                for(int i=0;i<2;i++){ wmma::load_matrix_sync(ah[i],pa_h+i*16*ALD,ALD); \
                                      wmma::load_matrix_sync(al2[i],pa_l+i*16*ALD,ALD); } \
                _Pragma("unroll")                                                \
                for(int j=0;j<4;j++){ wmma::load_matrix_sync(bh[j],pb_h+j*16,BLD); \
                                      wmma::load_matrix_sync(bl2[j],pb_l+j*16,BLD); } \
                _Pragma("unroll")                                                \
                for(int i=0;i<2;i++)                                             \
                    _Pragma("unroll")                                            \
                    for(int j=0;j<4;j++){                                        \
                        wmma::mma_sync(acc[i][j],ah[i],bh[j],acc[i][j]);         \
                        wmma::mma_sync(acc[i][j],al2[i],bh[j],acc[i][j]);        \
                        wmma::mma_sync(acc[i][j],ah[i],bl2[j],acc[i][j]);        \
                    }                                                            \
            }                                                                    \
        }while(0)

        LOADT(0); STORET(0);
        __syncthreads();
        int buf=0;
        for(int k0=BK;k0<E.K;k0+=BK){
            LOADT(k0);
            STORET(buf^1);      // staged regs released before compute
            COMPUTE(buf);
            __syncthreads();
            buf^=1;
        }
        COMPUTE(buf);
        __syncthreads();
        #undef LOADT
        #undef STORET
        #undef COMPUTE

        // epilogue: per-warp 32x64 region via smem
        float* ep = eps + wid*2048;
        #pragma unroll
        for(int i=0;i<2;i++)
            #pragma unroll
            for(int j=0;j<4;j++)
                wmma::store_matrix_sync(ep + i*16*64 + j*16, acc[i][j], 64, wmma::mem_row_major);
        __syncwarp();
        int c0 = n0 + wc*64 + lid*2;
        for(int r2=0;r2<32;r2++){
            int row = m0 + wr*32 + r2;
            if(row >= E.M) break;
            float2 vv = *(float2*)(ep + r2*64 + lid*2);
            float* crow = E.C + (size_t)row*E.N + c0;
            if(E.atomic_ep){ atomicAdd(crow,vv.x); atomicAdd(crow+1,vv.y); }
            else { *(float2*)crow = make_float2(vv.x+E.bias[c0], vv.y+E.bias[c0+1]); }
        }
        __syncthreads();
    }
}

static Entry mkent(const float* A,int lda,const __nv_bfloat16* bh,const __nv_bfloat16* bl,int ldb,
                   float* C,const float* bias,int M,int N,int K,int atomic_ep,int mode,int rr,const float* cnt){
    Entry e; e.A=A; e.Bh=bh; e.Bl=bl; e.bias=bias; e.cnt=cnt; e.C=C;
    e.M=M; e.N=N; e.K=K; e.lda=lda; e.ldb=ldb;
    e.atomic_ep=atomic_ep; e.mode=mode; e.rr=rr;
    e.tiles_n=N/128; e.ntiles=((M+127)/128)*e.tiles_n;
    return e;
}

extern "C" void kernel_launch(void* const* d_in, const int* in_sizes, int n_in, void* d_out, int out_size){
    const float* x=(const float*)d_in[0];
    const int* eidx=(const int*)d_in[1];
    const int* src=eidx; const int* dst=eidx+EE;
    const int* et=(const int*)d_in[2];
    const float* hprev=(const float*)d_in[3];
    const float* W1=(const float*)d_in[4];   const float* root1=(const float*)d_in[5];  const float* b1=(const float*)d_in[6];
    const float* W2=(const float*)d_in[7];   const float* root2=(const float*)d_in[8];  const float* b2=(const float*)d_in[9];
    const float* Wq=(const float*)d_in[10];  const float* bq=(const float*)d_in[11];
    const float* Wk=(const float*)d_in[12];  const float* bk=(const float*)d_in[13];
    const float* Wv=(const float*)d_in[14];  const float* bv=(const float*)d_in[15];
    const float* Wskip=(const float*)d_in[16]; const float* bskip=(const float*)d_in[17];
    const float* W_ih=(const float*)d_in[18]; const float* b_ih=(const float*)d_in[19];
    const float* W_hh=(const float*)d_in[20]; const float* b_hh=(const float*)d_in[21];
    float* out=(float*)d_out;

    static float* pool=nullptr; static float* cnt; static int* smax; static float* denom;
    static __nv_bfloat16 *wh,*wl;
    if(!pool){
        void* p;
        cudaGetSymbolAddress(&p,g_pool); pool=(float*)p;
        cudaGetSymbolAddress(&p,g_cnt); cnt=(float*)p;
        cudaGetSymbolAddress(&p,g_smax); smax=(int*)p;
        cudaGetSymbolAddress(&p,g_denom); denom=(float*)p;
        cudaGetSymbolAddress(&p,g_wh); wh=(__nv_bfloat16*)p;
        cudaGetSymbolAddress(&p,g_wl); wl=(__nv_bfloat16*)p;
        cudaFuncSetAttribute(k_bgemm, cudaFuncAttributeMaxDynamicSharedMemorySize, SMEM_DYN);
    }
    float* agg=pool+OFF_AGG; float* h1=pool+OFF_H1; float* h2=pool+OFF_H2;
    float* q=pool+OFF_Q; float* k=pool+OFF_K; float* v=pool+OFF_V;
    float* attn=pool+OFF_ATTN; float* score=pool+OFF_SCORE;
    float* gh=pool+OFF_GHX; float* gi=pool+OFF_GI;

    const int T=256, GB=304;
    int eW=(EE*32+T-1)/T;

    k_tick0<<<1,32>>>();
    { // weight conversion
        WTab wt; int idx=0; int sz[10];
        auto add=[&](const float* W,int K,int N,int tr,int off){ wt.e[idx]=WEnt{W,wh+off,wl+off,K,N,tr}; sz[idx]=N*K; idx++; };
        add(W1,512,256,0,WO_W1);
        add(W2,1024,256,0,WO_W2);
        add(root1,128,256,0,WO_R1);
        add(root2,256,256,0,WO_R2);
        add(Wq,256,256,0,WO_Q); add(Wk,256,256,0,WO_KW); add(Wv,256,256,0,WO_VW); add(Wskip,256,256,0,WO_SK);
        add(W_ih,256,768,1,WO_IH); add(W_hh,256,768,1,WO_HH);
        wt.off[0]=0; for(int i=0;i<10;i++) wt.off[i+1]=wt.off[i]+sz[i];
        wt.tot=wt.off[10];
        k_wconv<<<2048,T>>>(wt);
    }
    k_zero_f4<<<(NN*RR/4+T-1)/T,T>>>((float4*)cnt,(size_t)NN*RR/4);
    k_count<<<(EE+T-1)/T,T>>>(dst,et,cnt,EE);

    k_zero_f4<<<2048,T>>>((float4*)agg,(size_t)NN*RR*FIN/4);
    k_scatter<<<eW,T>>>(x,src,dst,et,agg,EE,FIN,0);
    k_seed_bias<<<1024,T>>>(h1,b1,NN,FH);
    { // batch 1: RGCN1 (root + 4 relations, atomic) + gh
        Batch bt; bt.slot=0; bt.ng=6;
        bt.e[0]=mkent(x,FIN, wh+WO_R1,wl+WO_R1,FH, h1,nullptr, NN,FH,FIN, 1,0,0,nullptr);
        for(int r=0;r<RR;r++)
            bt.e[1+r]=mkent(agg+r*FIN,RR*FIN, wh+WO_W1+r*FIN*FH,wl+WO_W1+r*FIN*FH,FH,
                            h1,nullptr, NN,FH,FIN, 1,2,r,cnt);
        bt.e[5]=mkent(hprev,FH, wh+WO_HH,wl+WO_HH,G3, gh,b_hh, NN,G3,FH, 0,0,0,nullptr);
        bt.total=0; for(int i=0;i<bt.ng;i++) bt.total+=bt.e[i].ntiles;
        k_bgemm<<<GB,T,SMEM_DYN>>>(bt);
    }
    k_zero_f4<<<4096,T>>>((float4*)agg,(size_t)NN*RR*FH/4);
    k_scatter<<<eW,T>>>(h1,src,dst,et,agg,EE,FH,1);
    k_seed_bias<<<1024,T>>>(h2,b2,NN,FH);
    { // batch 2: RGCN2
        Batch bt; bt.slot=1; bt.ng=5;
        bt.e[0]=mkent(h1,FH, wh+WO_R2,wl+WO_R2,FH, h2,nullptr, NN,FH,FH, 1,1,0,nullptr);
        for(int r=0;r<RR;r++)
            bt.e[1+r]=mkent(agg+r*FH,RR*FH, wh+WO_W2+r*FH*FH,wl+WO_W2+r*FH*FH,FH,
                            h2,nullptr, NN,FH,FH, 1,2,r,cnt);
        bt.total=0; for(int i=0;i<bt.ng;i++) bt.total+=bt.e[i].ntiles;
        k_bgemm<<<GB,T,SMEM_DYN>>>(bt);
    }
    { // batch 3: q/k/v/skip
        Batch bt; bt.slot=2; bt.ng=4;
        bt.e[0]=mkent(h2,FH, wh+WO_Q, wl+WO_Q, FH, q,   bq,   NN,FH,FH, 0,1,0,nullptr);
        bt.e[1]=mkent(h2,FH, wh+WO_KW,wl+WO_KW,FH, k,   bk,   NN,FH,FH, 0,1,0,nullptr);
        bt.e[2]=mkent(h2,FH, wh+WO_VW,wl+WO_VW,FH, v,   bv,   NN,FH,FH, 0,1,0,nullptr);
        bt.e[3]=mkent(h2,FH, wh+WO_SK,wl+WO_SK,FH, attn,bskip,NN,FH,FH, 0,1,0,nullptr);
        bt.total=0; for(int i=0;i<bt.ng;i++) bt.total+=bt.e[i].ntiles;
        k_bgemm<<<GB,T,SMEM_DYN>>>(bt);
    }
    k_init_attn<<<(NN*NH+T-1)/T,T>>>(smax,denom,NN*NH);
    k_score<<<eW,T>>>(q,k,src,dst,score,smax,EE);
    k_expsum<<<(EE*NH+T-1)/T,T>>>(score,dst,smax,denom,EE);
    k_attn<<<eW,T>>>(score,denom,v,src,dst,attn,EE);
    { // batch 4: gi
        Batch bt; bt.slot=3; bt.ng=1;
        bt.e[0]=mkent(attn,FH, wh+WO_IH,wl+WO_IH,G3, gi,b_ih, NN,G3,FH, 0,0,0,nullptr);
        bt.total=bt.e[0].ntiles;
        k_bgemm<<<GB,T,SMEM_DYN>>>(bt);
    }
    k_gru<<<((size_t)NN*FH+T-1)/T,T>>>(gi,gh,hprev,out);
}